// round 6
// baseline (speedup 1.0000x reference)
#include <cuda_runtime.h>
#include <math.h>

#define B_    1024
#define D_    8
#define P_    128
#define NPTS  1024
#define H_    256
#define W_    256
#define NTHREADS 128
#define PTS_PER_THREAD 8

#define GRAVITY     9.8f
#define DT          0.01f
#define TORQUE_LIM  200.0f
#define K_STIFF     5000.0f
#define K_LON       0.5f
#define K_LAT       0.5f
#define BODY_MASS   40.0f
#define MAX_COORD   6.4f
#define IC_SCALE    (-57.73502691896258f)   /* -sqrt(3)/SIGMA */
#define UV_SCALE    19.921875f              /* (W-1)/(2*MAX_COORD) */

// output offsets (floats) — all multiples of 4 => float4-aligned
#define OFF_NX   0
#define OFF_NXD  3072
#define OFF_NQ   6144
#define OFF_NOM  10240
#define OFF_NTH  13312
#define OFF_XDD  21504
#define OFF_OMD  24576
#define OFF_THD  27648
#define OFF_FS   35840
#define OFF_FF   3181568
#define OFF_IC   6327296
#define OFF_TQ   7375872
#define OFF_RP   7378944
#define OFF_THR  10524672

__device__ __forceinline__ float warp_sum(float v) {
#pragma unroll
    for (int o = 16; o; o >>= 1) v += __shfl_xor_sync(0xffffffffu, v, o);
    return v;
}

__device__ __forceinline__ float tanh_fast(float x) {
    float y;
    asm("tanh.approx.f32 %0, %1;" : "=f"(y) : "f"(x));
    return y;
}

__global__ __launch_bounds__(NTHREADS, 8)
void phys_kernel(const float* __restrict__ x_in,
                 const float* __restrict__ xd_in,
                 const float* __restrict__ q_in,
                 const float* __restrict__ om_in,
                 const float* __restrict__ th_in,
                 const float* __restrict__ ctrl_in,
                 const float* __restrict__ zg_in,
                 const float* __restrict__ zgg_in,
                 const float* __restrict__ jp_in,
                 const float* __restrict__ jlp_in,
                 const float* __restrict__ jlc_in,
                 const float* __restrict__ dpi_in,
                 const float* __restrict__ dpm_in,
                 const float* __restrict__ bcog_in,
                 const float* __restrict__ binert_in,
                 const float* __restrict__ ddir_in,
                 float* __restrict__ out)
{
    const int b   = blockIdx.x;
    const int tid = threadIdx.x;
    const int w   = tid >> 5;          // warp id (0..3)
    const int dpart = tid >> 4;        // part id for this thread's 8 points

    // per-point staging (phase1 -> phase2), overwritten by fs/ff in phase2
    __shared__ float s_rx[NPTS], s_ry[NPTS], s_rz[NPTS];   // -> fsx, fsy, fsz
    __shared__ float s_gx[NPTS], s_gy[NPTS], s_dh[NPTS];   // -> ffx, ffy, ffz

    __shared__ float sR[9];
    __shared__ float s_c[D_], s_sn[D_];
    __shared__ float s_jp[D_][3];
    __shared__ float s_cogl[D_][3];
    __shared__ float s_rotI[D_][9];
    __shared__ float s_tl[D_][3];
    __shared__ float s_thr[D_][3];
    __shared__ float s_Iov[9], s_M9[9];
    __shared__ float s_gcog[3], s_gdd[3], s_inertia[9];
    __shared__ float s_x[3], s_xd[3], s_om[3];
    __shared__ float s_tm;
    __shared__ float s_red[32];

    // ------------------ Phase 0a: per-part prep ------------------
    if (tid < D_) {
        const int d = tid;
        const float th = th_in[b * D_ + d];
        const float c = cosf(th), s = sinf(th);
        s_c[d] = c; s_sn[d] = s;
        const float jpx = jp_in[d*3+0], jpy = jp_in[d*3+1], jpz = jp_in[d*3+2];
        s_jp[d][0] = jpx; s_jp[d][1] = jpy; s_jp[d][2] = jpz;
        const float lx = jlc_in[d*3+0], ly = jlc_in[d*3+1], lz = jlc_in[d*3+2];
        s_cogl[d][0] =  c*lx + s*lz + jpx;
        s_cogl[d][1] =  ly + jpy;
        s_cogl[d][2] = -s*lx + c*lz + jpz;
        float I9[9];
#pragma unroll
        for (int k = 0; k < 9; k++) I9[k] = dpi_in[d*9 + k];
        float M[9];
        M[0] =  c*I9[0] + s*I9[6];  M[1] =  c*I9[1] + s*I9[7];  M[2] =  c*I9[2] + s*I9[8];
        M[3] =  I9[3];              M[4] =  I9[4];              M[5] =  I9[5];
        M[6] = -s*I9[0] + c*I9[6];  M[7] = -s*I9[1] + c*I9[7];  M[8] = -s*I9[2] + c*I9[8];
#pragma unroll
        for (int r = 0; r < 3; r++) {
            s_rotI[d][r*3+0] =  M[r*3+0]*c + M[r*3+2]*s;
            s_rotI[d][r*3+1] =  M[r*3+1];
            s_rotI[d][r*3+2] = -M[r*3+0]*s + M[r*3+2]*c;
        }
        const float dx = ddir_in[0], dy = ddir_in[1], dz = ddir_in[2];
        const float vc = ctrl_in[b*2*D_ + d];
        s_tl[d][0] = ( c*dx + s*dz) * vc;
        s_tl[d][1] = ( dy          ) * vc;
        s_tl[d][2] = (-s*dx + c*dz) * vc;
        float td = ctrl_in[b*2*D_ + D_ + d];
        td = fminf(fmaxf(td, -0.5f), 0.5f);
        out[OFF_THD + (size_t)b*D_ + d] = td;
        float nth = th + td * DT;
        out[OFF_NTH + (size_t)b*D_ + d] = fminf(fmaxf(nth, -1.0f), 1.0f);
    }
    if (tid == 8) {
        const float qw = q_in[b*4+0], qx = q_in[b*4+1], qy = q_in[b*4+2], qz = q_in[b*4+3];
        sR[0] = 1.0f - 2.0f*(qy*qy + qz*qz);
        sR[1] = 2.0f*(qx*qy - qw*qz);
        sR[2] = 2.0f*(qx*qz + qw*qy);
        sR[3] = 2.0f*(qx*qy + qw*qz);
        sR[4] = 1.0f - 2.0f*(qx*qx + qz*qz);
        sR[5] = 2.0f*(qy*qz - qw*qx);
        sR[6] = 2.0f*(qx*qz - qw*qy);
        sR[7] = 2.0f*(qy*qz + qw*qx);
        sR[8] = 1.0f - 2.0f*(qx*qx + qy*qy);
    }
    if (tid == 9) {
#pragma unroll
        for (int k = 0; k < 3; k++) {
            s_x[k]  = x_in[b*3+k];
            s_xd[k] = xd_in[b*3+k];
            s_om[k] = om_in[b*3+k];
        }
    }
    __syncthreads();

    // ------------------ Phase 0b: warp 0 only, overlapped with phase 1 ----
    if (tid < 32) {
        float m[D_];
        float tm = BODY_MASS;
#pragma unroll
        for (int d = 0; d < D_; d++) { m[d] = dpm_in[d]; tm += m[d]; }
        float cg0 = 0.f, cg1 = 0.f, cg2 = 0.f;
#pragma unroll
        for (int d = 0; d < D_; d++) {
            cg0 += s_cogl[d][0] * m[d];
            cg1 += s_cogl[d][1] * m[d];
            cg2 += s_cogl[d][2] * m[d];
        }
        const float bc0 = bcog_in[0], bc1 = bcog_in[1], bc2 = bcog_in[2];
        const float itm = 1.0f / tm;
        cg0 = (cg0 + BODY_MASS*bc0) * itm;
        cg1 = (cg1 + BODY_MASS*bc1) * itm;
        cg2 = (cg2 + BODY_MASS*bc2) * itm;

        if (tid < 24) {
            const int d = tid / 3, k = tid - 3*(tid/3);
            s_thr[d][k] = sR[k*3+0]*s_tl[d][0] + sR[k*3+1]*s_tl[d][1] + sR[k*3+2]*s_tl[d][2];
        }
        if (tid < 9) {
            const int r = tid / 3, c = tid - 3*(tid/3);
            float Iv = binert_in[tid];
#pragma unroll
            for (int d = 0; d < D_; d++) {
                const float ddx = s_cogl[d][0]-cg0, ddy = s_cogl[d][1]-cg1, ddz = s_cogl[d][2]-cg2;
                const float s2 = ddx*ddx + ddy*ddy + ddz*ddz;
                const float er = (r==0)?ddx:(r==1)?ddy:ddz;
                const float ec = (c==0)?ddx:(c==1)?ddy:ddz;
                Iv += s_rotI[d][tid] + m[d]*(((r==c)?s2:0.0f) - er*ec);
            }
            {
                const float ddx = bc0-cg0, ddy = bc1-cg1, ddz = bc2-cg2;
                const float s2 = ddx*ddx + ddy*ddy + ddz*ddz;
                const float er = (r==0)?ddx:(r==1)?ddy:ddz;
                const float ec = (c==0)?ddx:(c==1)?ddy:ddz;
                Iv += BODY_MASS*(((r==c)?s2:0.0f) - er*ec);
            }
            s_Iov[tid] = Iv;
        }
        if (tid >= 9 && tid < 12) {
            const int k = tid - 9;
            s_gcog[k] = sR[k*3+0]*cg0 + sR[k*3+1]*cg1 + sR[k*3+2]*cg2 + s_x[k];
        }
        if (tid >= 12 && tid < 15) {
            const int k = tid - 12;
            s_gdd[k] = sR[k*3+0]*ddir_in[0] + sR[k*3+1]*ddir_in[1] + sR[k*3+2]*ddir_in[2];
        }
        if (tid == 15) s_tm = tm;
        __syncwarp();
        if (tid < 9) {
            const int r = tid / 3, c = tid - 3*(tid/3);
            s_M9[tid] = sR[r*3+0]*s_Iov[c] + sR[r*3+1]*s_Iov[3+c] + sR[r*3+2]*s_Iov[6+c];
        }
        __syncwarp();
        if (tid < 9) {
            const int r = tid / 3, c = tid - 3*(tid/3);
            s_inertia[tid] = s_M9[r*3+0]*sR[c*3+0] + s_M9[r*3+1]*sR[c*3+1] + s_M9[r*3+2]*sR[c*3+2];
        }
    }

    // ------------------ Phase 1: 8 consecutive points per thread ----------
    const float* __restrict__ zg  = zg_in  + (size_t)b * (H_*W_);
    const float* __restrict__ zgx = zgg_in + (size_t)b * (2*H_*W_);
    const float* __restrict__ zgy = zgx + H_*W_;

    const float cw  = s_c[dpart],  sw  = s_sn[dpart];
    const float jpx = s_jp[dpart][0], jpy = s_jp[dpart][1], jpz = s_jp[dpart][2];
    const float x0 = s_x[0], x1 = s_x[1], x2 = s_x[2];

    float icsum = 0.0f;
    float icbuf[PTS_PER_THREAD];

#pragma unroll
    for (int g = 0; g < 2; g++) {
        const float4* jl4 = reinterpret_cast<const float4*>(jlp_in) + 6*tid + 3*g;
        const float4 A0 = __ldg(jl4), A1 = __ldg(jl4+1), A2 = __ldg(jl4+2);
        const float jx[4] = {A0.x, A0.w, A1.z, A2.y};
        const float jy[4] = {A0.y, A1.x, A1.w, A2.z};
        const float jz[4] = {A0.z, A1.y, A2.x, A2.w};

#pragma unroll
        for (int j = 0; j < 4; j++) {
            const int i = PTS_PER_THREAD*tid + 4*g + j;
            const float plx =  cw*jx[j] + sw*jz[j] + jpx;
            const float ply =  jy[j]                + jpy;
            const float plz = -sw*jx[j] + cw*jz[j] + jpz;
            const float rx = sR[0]*plx + sR[1]*ply + sR[2]*plz + x0;
            const float ry = sR[3]*plx + sR[4]*ply + sR[5]*plz + x1;
            const float rz = sR[6]*plx + sR[7]*ply + sR[8]*plz + x2;

            float u = (rx + MAX_COORD) * UV_SCALE;
            float v = (ry + MAX_COORD) * UV_SCALE;
            u = fminf(fmaxf(u, 0.0f), (float)(W_-1) - 1e-5f);
            v = fminf(fmaxf(v, 0.0f), (float)(H_-1) - 1e-5f);
            const int u0 = (int)floorf(u), v0 = (int)floorf(v);
            const float fu = u - (float)u0, fv = v - (float)v0;
            const int i00 = v0*W_ + u0;
            const int i10 = i00 + W_;

            const float z00 = __ldg(zg + i00),  z01 = __ldg(zg + i00 + 1);
            const float z10 = __ldg(zg + i10),  z11 = __ldg(zg + i10 + 1);
            const float x00 = __ldg(zgx + i00), x01 = __ldg(zgx + i00 + 1);
            const float x10 = __ldg(zgx + i10), x11 = __ldg(zgx + i10 + 1);
            const float y00 = __ldg(zgy + i00), y01 = __ldg(zgy + i00 + 1);
            const float y10 = __ldg(zgy + i10), y11 = __ldg(zgy + i10 + 1);

            const float gu = 1.0f - fu, gv = 1.0f - fv;
            const float zs = (z00*gu + z01*fu)*gv + (z10*gu + z11*fu)*fv;
            const float gx = (x00*gu + x01*fu)*gv + (x10*gu + x11*fu)*fv;
            const float gy = (y00*gu + y01*fu)*gv + (y10*gu + y11*fu)*fv;

            const float nrm = sqrtf(gx*gx + gy*gy + 1.0f);
            const float inv = __fdividef(1.0f, nrm + 1e-8f);
            const float dh = (rz - zs) * inv;     // nz == inv
            const float ic = 0.5f * (1.0f + tanh_fast(dh * IC_SCALE));

            s_rx[i] = rx; s_ry[i] = ry; s_rz[i] = rz;
            s_gx[i] = gx; s_gy[i] = gy; s_dh[i] = dh;
            icbuf[4*g+j] = ic;
            icsum += ic;
        }
    }

    // in_contact out: 2 float4 of own points
    {
        float4* ico = reinterpret_cast<float4*>(out + OFF_IC + (size_t)b*1024) + 2*tid;
        ico[0] = make_float4(icbuf[0], icbuf[1], icbuf[2], icbuf[3]);
        ico[1] = make_float4(icbuf[4], icbuf[5], icbuf[6], icbuf[7]);
    }

    {   // contact-count partials (4 warps)
        const float ws = warp_sum(icsum);
        if ((tid & 31) == 0) s_red[w] = ws;
    }
    __syncthreads();

    // robot_points copy-out: coalesced float4 from staged smem
    {
        float4* rpo = reinterpret_cast<float4*>(out + OFF_RP + (size_t)b*3072) + 6*tid;
#pragma unroll
        for (int k = 0; k < 6; k++) {
            float vv[4];
#pragma unroll
            for (int c = 0; c < 4; c++) {
                const int K = 4*k + c;          // compile-time
                const int p = 8*tid + K/3;
                const int r = K % 3;
                vv[c] = (r==0) ? s_rx[p] : (r==1) ? s_ry[p] : s_rz[p];
            }
            rpo[k] = make_float4(vv[0], vv[1], vv[2], vv[3]);
        }
    }

    // nc computed redundantly by all threads
    float nc = 0.0f;
#pragma unroll
    for (int w4 = 0; w4 < 4; w4++) nc += s_red[w4];
    nc = fmaxf(nc, 1.0f);
    const float inv_nc = __fdividef(1.0f, nc);
    const float kd = sqrtf(s_tm * K_STIFF * inv_nc);   // DAMPING_ALPHA*2 = 1

    // ------------------ Phase 2: forces ------------------
    const float gddx = s_gdd[0], gddy = s_gdd[1], gddz = s_gdd[2];
    const float ox = s_om[0], oy = s_om[1], oz = s_om[2];
    const float gc0 = s_gcog[0], gc1 = s_gcog[1], gc2 = s_gcog[2];
    const float xd0 = s_xd[0], xd1 = s_xd[1], xd2 = s_xd[2];
    const float thx = s_thr[dpart][0], thy = s_thr[dpart][1], thz = s_thr[dpart][2];

    float asx=0.f, asy=0.f, asz=0.f, tqx=0.f, tqy=0.f, tqz=0.f;

#pragma unroll
    for (int jj = 0; jj < PTS_PER_THREAD; jj++) {
        const int i = PTS_PER_THREAD*tid + jj;
        const float gx = s_gx[i], gy = s_gy[i], dh = s_dh[i];
        const float rx = s_rx[i], ry = s_ry[i], rz = s_rz[i];

        const float nrm = sqrtf(gx*gx + gy*gy + 1.0f);
        const float invn = __fdividef(1.0f, nrm + 1e-8f);
        const float nx = -gx*invn, ny = -gy*invn, nz = invn;
        const float ic = 0.5f * (1.0f + tanh_fast(dh * IC_SCALE));

        const float ccx = rx - gc0;
        const float ccy = ry - gc1;
        const float ccz = rz - gc2;
        const float vx = xd0 + oy*ccz - oz*ccy;
        const float vy = xd1 + oz*ccx - ox*ccz;
        const float vz = xd2 + ox*ccy - oy*ccx;
        const float xdn = vx*nx + vy*ny + vz*nz;
        const float coef = -(K_STIFF * (dh*ic) + kd * xdn) * ic * inv_nc;
        const float fsx = coef*nx, fsy = coef*ny, fsz = coef*nz;
        const float Nmag = fabsf(coef);       // |F_spring| since |n| == 1

        const float gdn = gddx*nx + gddy*ny + gddz*nz;
        float fwx = gddx - gdn*nx, fwy = gddy - gdn*ny, fwz = gddz - gdn*nz;
        {
            const float fn = sqrtf(fwx*fwx + fwy*fwy + fwz*fwz);
            const float iv = __fdividef(1.0f, fn + 1e-8f);
            fwx *= iv; fwy *= iv; fwz *= iv;
        }
        float ltx = fwy*nz - fwz*ny;
        float lty = fwz*nx - fwx*nz;
        float ltz = fwx*ny - fwy*nx;
        {
            const float ln = sqrtf(ltx*ltx + lty*lty + ltz*ltz);
            const float iv = __fdividef(1.0f, ln + 1e-8f);
            ltx *= iv; lty *= iv; ltz *= iv;
        }
        const float dvx = thx - vx;
        const float dvy = thy - vy;
        const float dvz = thz - vz;
        const float dvn = dvx*nx + dvy*ny + dvz*nz;
        const float tx = tanh_fast(dvx - dvn*nx);
        const float ty = tanh_fast(dvy - dvn*ny);
        const float tz = tanh_fast(dvz - dvn*nz);
        const float lon = tx*fwx + ty*fwy + tz*fwz;
        const float lat = tx*ltx + ty*lty + tz*ltz;
        const float c1 = K_LON * Nmag * lon;
        const float c2 = K_LAT * Nmag * lat;
        const float ffx = c1*fwx + c2*ltx;
        const float ffy = c1*fwy + c2*lty;
        const float ffz = c1*fwz + c2*ltz;

        const float ax = fsx + ffx, ay = fsy + ffy, az = fsz + ffz;
        asx += ax; asy += ay; asz += az;
        tqx += ccy*az - ccz*ay;
        tqy += ccz*ax - ccx*az;
        tqz += ccx*ay - ccy*ax;

        // overwrite staging in place (same thread, same index)
        s_rx[i] = fsx; s_ry[i] = fsy; s_rz[i] = fsz;
        s_gx[i] = ffx; s_gy[i] = ffy; s_dh[i] = ffz;
    }

    // thrust out (warp-uniform per thread, direct float4)
    {
        float4* tho = reinterpret_cast<float4*>(out + OFF_THR + (size_t)b*3072) + 6*tid;
        const float4 t0 = make_float4(thx, thy, thz, thx);
        const float4 t1 = make_float4(thy, thz, thx, thy);
        const float4 t2 = make_float4(thz, thx, thy, thz);
        tho[0] = t0; tho[1] = t1; tho[2] = t2;
        tho[3] = t0; tho[4] = t1; tho[5] = t2;
    }

    {   // reduce 6 sums (4 warps)
        float r[6] = {asx, asy, asz, tqx, tqy, tqz};
#pragma unroll
        for (int j = 0; j < 6; j++) {
            const float ws = warp_sum(r[j]);
            if ((tid & 31) == 0) s_red[j*4 + w] = ws;
        }
    }
    __syncthreads();

    // F_spring / F_friction copy-out: coalesced float4 from staged smem
    {
        float4* fso = reinterpret_cast<float4*>(out + OFF_FS + (size_t)b*3072) + 6*tid;
        float4* ffo = reinterpret_cast<float4*>(out + OFF_FF + (size_t)b*3072) + 6*tid;
#pragma unroll
        for (int k = 0; k < 6; k++) {
            float vs[4], vf[4];
#pragma unroll
            for (int c = 0; c < 4; c++) {
                const int K = 4*k + c;
                const int p = 8*tid + K/3;
                const int r = K % 3;
                vs[c] = (r==0) ? s_rx[p] : (r==1) ? s_ry[p] : s_rz[p];
                vf[c] = (r==0) ? s_gx[p] : (r==1) ? s_gy[p] : s_dh[p];
            }
            fso[k] = make_float4(vs[0], vs[1], vs[2], vs[3]);
            ffo[k] = make_float4(vf[0], vf[1], vf[2], vf[3]);
        }
    }

    // ------------------ Phase 3: solve + integrate ------------------
    if (tid == 0) {
        float as0 = 0.f, as1 = 0.f, as2 = 0.f, t0 = 0.f, t1 = 0.f, t2 = 0.f;
#pragma unroll
        for (int w4 = 0; w4 < 4; w4++) {
            as0 += s_red[0*4 + w4]; as1 += s_red[1*4 + w4]; as2 += s_red[2*4 + w4];
            t0  += s_red[3*4 + w4]; t1  += s_red[4*4 + w4]; t2  += s_red[5*4 + w4];
        }
        const float tqcx = fminf(fmaxf(t0, -TORQUE_LIM), TORQUE_LIM);
        const float tqcy = fminf(fmaxf(t1, -TORQUE_LIM), TORQUE_LIM);
        const float tqcz = fminf(fmaxf(t2, -TORQUE_LIM), TORQUE_LIM);
        out[OFF_TQ + (size_t)b*3 + 0] = tqcx;
        out[OFF_TQ + (size_t)b*3 + 1] = tqcy;
        out[OFF_TQ + (size_t)b*3 + 2] = tqcz;

        const double a00=s_inertia[0], a01=s_inertia[1], a02=s_inertia[2];
        const double a10=s_inertia[3], a11=s_inertia[4], a12=s_inertia[5];
        const double a20=s_inertia[6], a21=s_inertia[7], a22=s_inertia[8];
        const double bx=tqcx, by=tqcy, bz=tqcz;
        const double c00 = a11*a22 - a12*a21;
        const double c01 = a10*a22 - a12*a20;
        const double c02 = a10*a21 - a11*a20;
        const double det = a00*c00 - a01*c01 + a02*c02;
        const double inv = 1.0/det;
        const double odx = (bx*c00 - a01*(by*a22 - a12*bz) + a02*(by*a21 - a11*bz)) * inv;
        const double ody = (a00*(by*a22 - a12*bz) - bx*c01 + a02*(a10*bz - by*a20)) * inv;
        const double odz = (a00*(a11*bz - by*a21) - a01*(a10*bz - by*a20) + bx*c02) * inv;
        const float odxf=(float)odx, odyf=(float)ody, odzf=(float)odz;
        out[OFF_OMD + (size_t)b*3 + 0] = odxf;
        out[OFF_OMD + (size_t)b*3 + 1] = odyf;
        out[OFF_OMD + (size_t)b*3 + 2] = odzf;

        const float itm = __fdividef(1.0f, s_tm);
        const float xddx = as0 * itm;
        const float xddy = as1 * itm;
        const float xddz = (as2 - s_tm*GRAVITY) * itm;
        out[OFF_XDD + (size_t)b*3 + 0] = xddx;
        out[OFF_XDD + (size_t)b*3 + 1] = xddy;
        out[OFF_XDD + (size_t)b*3 + 2] = xddz;

        const float nxd0 = s_xd[0] + xddx*DT;
        const float nxd1 = s_xd[1] + xddy*DT;
        const float nxd2 = s_xd[2] + xddz*DT;
        out[OFF_NXD + (size_t)b*3 + 0] = nxd0;
        out[OFF_NXD + (size_t)b*3 + 1] = nxd1;
        out[OFF_NXD + (size_t)b*3 + 2] = nxd2;
        out[OFF_NX + (size_t)b*3 + 0] = s_x[0] + nxd0*DT;
        out[OFF_NX + (size_t)b*3 + 1] = s_x[1] + nxd1*DT;
        out[OFF_NX + (size_t)b*3 + 2] = s_x[2] + nxd2*DT;

        const float no0 = s_om[0] + odxf*DT;
        const float no1 = s_om[1] + odyf*DT;
        const float no2 = s_om[2] + odzf*DT;
        out[OFF_NOM + (size_t)b*3 + 0] = no0;
        out[OFF_NOM + (size_t)b*3 + 1] = no1;
        out[OFF_NOM + (size_t)b*3 + 2] = no2;

        const float aw = q_in[b*4+0], axq = q_in[b*4+1], ayq = q_in[b*4+2], azq = q_in[b*4+3];
        const float h = 0.5f * DT;
        const float dqw = h * (-(axq*no0 + ayq*no1 + azq*no2));
        const float dqx = h * ( aw*no0 + ayq*no2 - azq*no1);
        const float dqy = h * ( aw*no1 - axq*no2 + azq*no0);
        const float dqz = h * ( aw*no2 + axq*no1 - ayq*no0);
        const float nqw = aw + dqw, nqx = axq + dqx, nqy = ayq + dqy, nqz = azq + dqz;
        const float qn = sqrtf(nqw*nqw + nqx*nqx + nqy*nqy + nqz*nqz);
        const float qi = __fdividef(1.0f, qn + 1e-8f);
        out[OFF_NQ + (size_t)b*4 + 0] = nqw*qi;
        out[OFF_NQ + (size_t)b*4 + 1] = nqx*qi;
        out[OFF_NQ + (size_t)b*4 + 2] = nqy*qi;
        out[OFF_NQ + (size_t)b*4 + 3] = nqz*qi;
    }
}

extern "C" void kernel_launch(void* const* d_in, const int* in_sizes, int n_in,
                              void* d_out, int out_size)
{
    phys_kernel<<<B_, NTHREADS>>>(
        (const float*)d_in[0],  (const float*)d_in[1],  (const float*)d_in[2],
        (const float*)d_in[3],  (const float*)d_in[4],  (const float*)d_in[5],
        (const float*)d_in[6],  (const float*)d_in[7],  (const float*)d_in[8],
        (const float*)d_in[9],  (const float*)d_in[10], (const float*)d_in[11],
        (const float*)d_in[12], (const float*)d_in[13], (const float*)d_in[14],
        (const float*)d_in[15], (float*)d_out);
}

// round 7
// speedup vs baseline: 1.2056x; 1.2056x over previous
#include <cuda_runtime.h>
#include <math.h>

#define B_    1024
#define D_    8
#define P_    128
#define NPTS  1024
#define H_    256
#define W_    256
#define NTHREADS 256

#define GRAVITY     9.8f
#define DT          0.01f
#define TORQUE_LIM  200.0f
#define K_STIFF     5000.0f
#define K_LON       0.5f
#define K_LAT       0.5f
#define BODY_MASS   40.0f
#define MAX_COORD   6.4f
#define IC_SCALE    (-57.73502691896258f)   /* -sqrt(3)/SIGMA */
#define UV_SCALE    19.921875f              /* (W-1)/(2*MAX_COORD) */

// output offsets (floats) — all multiples of 4 => float4-aligned
#define OFF_NX   0
#define OFF_NXD  3072
#define OFF_NQ   6144
#define OFF_NOM  10240
#define OFF_NTH  13312
#define OFF_XDD  21504
#define OFF_OMD  24576
#define OFF_THD  27648
#define OFF_FS   35840
#define OFF_FF   3181568
#define OFF_IC   6327296
#define OFF_TQ   7375872
#define OFF_RP   7378944
#define OFF_THR  10524672

__device__ __forceinline__ float warp_sum(float v) {
#pragma unroll
    for (int o = 16; o; o >>= 1) v += __shfl_xor_sync(0xffffffffu, v, o);
    return v;
}

__device__ __forceinline__ float tanh_fast(float x) {
    float y;
    asm("tanh.approx.f32 %0, %1;" : "=f"(y) : "f"(x));
    return y;
}

__global__ __launch_bounds__(NTHREADS)
void phys_kernel(const float* __restrict__ x_in,
                 const float* __restrict__ xd_in,
                 const float* __restrict__ q_in,
                 const float* __restrict__ om_in,
                 const float* __restrict__ th_in,
                 const float* __restrict__ ctrl_in,
                 const float* __restrict__ zg_in,
                 const float* __restrict__ zgg_in,
                 const float* __restrict__ jp_in,
                 const float* __restrict__ jlp_in,
                 const float* __restrict__ jlc_in,
                 const float* __restrict__ dpi_in,
                 const float* __restrict__ dpm_in,
                 const float* __restrict__ bcog_in,
                 const float* __restrict__ binert_in,
                 const float* __restrict__ ddir_in,
                 float* __restrict__ out)
{
    const int b   = blockIdx.x;
    const int tid = threadIdx.x;
    const int w   = tid >> 5;   // warp id == part id

    __shared__ float sR[9];
    __shared__ float s_c[D_], s_sn[D_];
    __shared__ float s_jp[D_][3];
    __shared__ float s_cogl[D_][3];
    __shared__ float s_rotI[D_][9];
    __shared__ float s_tl[D_][3];
    __shared__ float s_thr[D_][3];
    __shared__ float s_Iov[9], s_M9[9];
    __shared__ float s_gcog[3], s_gdd[3], s_inertia[9];
    __shared__ float s_x[3], s_xd[3], s_om[3];
    __shared__ float s_tm;
    __shared__ float s_red[48];

    // ------------------ Phase 0a: per-part prep ------------------
    if (tid < D_) {
        const int d = tid;
        const float th = th_in[b * D_ + d];
        const float c = cosf(th), s = sinf(th);
        s_c[d] = c; s_sn[d] = s;
        const float jpx = jp_in[d*3+0], jpy = jp_in[d*3+1], jpz = jp_in[d*3+2];
        s_jp[d][0] = jpx; s_jp[d][1] = jpy; s_jp[d][2] = jpz;
        const float lx = jlc_in[d*3+0], ly = jlc_in[d*3+1], lz = jlc_in[d*3+2];
        s_cogl[d][0] =  c*lx + s*lz + jpx;
        s_cogl[d][1] =  ly + jpy;
        s_cogl[d][2] = -s*lx + c*lz + jpz;
        float I9[9];
#pragma unroll
        for (int k = 0; k < 9; k++) I9[k] = dpi_in[d*9 + k];
        float M[9];
        M[0] =  c*I9[0] + s*I9[6];  M[1] =  c*I9[1] + s*I9[7];  M[2] =  c*I9[2] + s*I9[8];
        M[3] =  I9[3];              M[4] =  I9[4];              M[5] =  I9[5];
        M[6] = -s*I9[0] + c*I9[6];  M[7] = -s*I9[1] + c*I9[7];  M[8] = -s*I9[2] + c*I9[8];
#pragma unroll
        for (int r = 0; r < 3; r++) {
            s_rotI[d][r*3+0] =  M[r*3+0]*c + M[r*3+2]*s;
            s_rotI[d][r*3+1] =  M[r*3+1];
            s_rotI[d][r*3+2] = -M[r*3+0]*s + M[r*3+2]*c;
        }
        const float dx = ddir_in[0], dy = ddir_in[1], dz = ddir_in[2];
        const float vc = ctrl_in[b*2*D_ + d];
        s_tl[d][0] = ( c*dx + s*dz) * vc;
        s_tl[d][1] = ( dy          ) * vc;
        s_tl[d][2] = (-s*dx + c*dz) * vc;
        float td = ctrl_in[b*2*D_ + D_ + d];
        td = fminf(fmaxf(td, -0.5f), 0.5f);
        out[OFF_THD + (size_t)b*D_ + d] = td;
        float nth = th + td * DT;
        out[OFF_NTH + (size_t)b*D_ + d] = fminf(fmaxf(nth, -1.0f), 1.0f);
    }
    if (tid == 8) {
        const float qw = q_in[b*4+0], qx = q_in[b*4+1], qy = q_in[b*4+2], qz = q_in[b*4+3];
        sR[0] = 1.0f - 2.0f*(qy*qy + qz*qz);
        sR[1] = 2.0f*(qx*qy - qw*qz);
        sR[2] = 2.0f*(qx*qz + qw*qy);
        sR[3] = 2.0f*(qx*qy + qw*qz);
        sR[4] = 1.0f - 2.0f*(qx*qx + qz*qz);
        sR[5] = 2.0f*(qy*qz - qw*qx);
        sR[6] = 2.0f*(qx*qz - qw*qy);
        sR[7] = 2.0f*(qy*qz + qw*qx);
        sR[8] = 1.0f - 2.0f*(qx*qx + qy*qy);
    }
    if (tid == 9) {
#pragma unroll
        for (int k = 0; k < 3; k++) {
            s_x[k]  = x_in[b*3+k];
            s_xd[k] = xd_in[b*3+k];
            s_om[k] = om_in[b*3+k];
        }
    }
    __syncthreads();

    // ------------------ Phase 0b: warp 0 only, overlapped with phase 1 ----
    if (tid < 32) {
        float m[D_];
        float tm = BODY_MASS;
#pragma unroll
        for (int d = 0; d < D_; d++) { m[d] = dpm_in[d]; tm += m[d]; }
        float cg0 = 0.f, cg1 = 0.f, cg2 = 0.f;
#pragma unroll
        for (int d = 0; d < D_; d++) {
            cg0 += s_cogl[d][0] * m[d];
            cg1 += s_cogl[d][1] * m[d];
            cg2 += s_cogl[d][2] * m[d];
        }
        const float bc0 = bcog_in[0], bc1 = bcog_in[1], bc2 = bcog_in[2];
        const float itm = 1.0f / tm;
        cg0 = (cg0 + BODY_MASS*bc0) * itm;
        cg1 = (cg1 + BODY_MASS*bc1) * itm;
        cg2 = (cg2 + BODY_MASS*bc2) * itm;

        if (tid < 24) {
            const int d = tid / 3, k = tid - 3*(tid/3);
            s_thr[d][k] = sR[k*3+0]*s_tl[d][0] + sR[k*3+1]*s_tl[d][1] + sR[k*3+2]*s_tl[d][2];
        }
        if (tid < 9) {
            const int r = tid / 3, c = tid - 3*(tid/3);
            float Iv = binert_in[tid];
#pragma unroll
            for (int d = 0; d < D_; d++) {
                const float ddx = s_cogl[d][0]-cg0, ddy = s_cogl[d][1]-cg1, ddz = s_cogl[d][2]-cg2;
                const float s2 = ddx*ddx + ddy*ddy + ddz*ddz;
                const float er = (r==0)?ddx:(r==1)?ddy:ddz;
                const float ec = (c==0)?ddx:(c==1)?ddy:ddz;
                Iv += s_rotI[d][tid] + m[d]*(((r==c)?s2:0.0f) - er*ec);
            }
            {
                const float ddx = bc0-cg0, ddy = bc1-cg1, ddz = bc2-cg2;
                const float s2 = ddx*ddx + ddy*ddy + ddz*ddz;
                const float er = (r==0)?ddx:(r==1)?ddy:ddz;
                const float ec = (c==0)?ddx:(c==1)?ddy:ddz;
                Iv += BODY_MASS*(((r==c)?s2:0.0f) - er*ec);
            }
            s_Iov[tid] = Iv;
        }
        if (tid >= 9 && tid < 12) {
            const int k = tid - 9;
            s_gcog[k] = sR[k*3+0]*cg0 + sR[k*3+1]*cg1 + sR[k*3+2]*cg2 + s_x[k];
        }
        if (tid >= 12 && tid < 15) {
            const int k = tid - 12;
            s_gdd[k] = sR[k*3+0]*ddir_in[0] + sR[k*3+1]*ddir_in[1] + sR[k*3+2]*ddir_in[2];
        }
        if (tid == 15) s_tm = tm;
        __syncwarp();
        if (tid < 9) {
            const int r = tid / 3, c = tid - 3*(tid/3);
            s_M9[tid] = sR[r*3+0]*s_Iov[c] + sR[r*3+1]*s_Iov[3+c] + sR[r*3+2]*s_Iov[6+c];
        }
        __syncwarp();
        if (tid < 9) {
            const int r = tid / 3, c = tid - 3*(tid/3);
            s_inertia[tid] = s_M9[r*3+0]*sR[c*3+0] + s_M9[r*3+1]*sR[c*3+1] + s_M9[r*3+2]*sR[c*3+2];
        }
    }

    // ------------------ Phase 1: 4 points/thread, batched gathers ---------
    const float* __restrict__ zg  = zg_in  + (size_t)b * (H_*W_);
    const float* __restrict__ zgx = zgg_in + (size_t)b * (2*H_*W_);
    const float* __restrict__ zgy = zgx + H_*W_;

    const float cw  = s_c[w],  sw  = s_sn[w];
    const float jpx = s_jp[w][0], jpy = s_jp[w][1], jpz = s_jp[w][2];
    const float x0 = s_x[0], x1 = s_x[1], x2 = s_x[2];

    const float4* jl4 = reinterpret_cast<const float4*>(jlp_in) + 3*tid;
    const float4 A0 = __ldg(jl4), A1 = __ldg(jl4+1), A2 = __ldg(jl4+2);
    const float jx[4] = {A0.x, A0.w, A1.z, A2.y};
    const float jy[4] = {A0.y, A1.x, A1.w, A2.z};
    const float jz[4] = {A0.z, A1.y, A2.x, A2.w};

    float rpx[4], rpy[4], rpz[4], fu[4], fv[4];
    int i00[4], i10[4];

    // stage A: all positions + addresses
#pragma unroll
    for (int j = 0; j < 4; j++) {
        const float plx =  cw*jx[j] + sw*jz[j] + jpx;
        const float ply =  jy[j]                + jpy;
        const float plz = -sw*jx[j] + cw*jz[j] + jpz;
        const float rx = sR[0]*plx + sR[1]*ply + sR[2]*plz + x0;
        const float ry = sR[3]*plx + sR[4]*ply + sR[5]*plz + x1;
        const float rz = sR[6]*plx + sR[7]*ply + sR[8]*plz + x2;
        rpx[j] = rx; rpy[j] = ry; rpz[j] = rz;

        float u = (rx + MAX_COORD) * UV_SCALE;
        float v = (ry + MAX_COORD) * UV_SCALE;
        u = fminf(fmaxf(u, 0.0f), (float)(W_-1) - 1e-5f);
        v = fminf(fmaxf(v, 0.0f), (float)(H_-1) - 1e-5f);
        const int u0 = (int)floorf(u), v0 = (int)floorf(v);
        fu[j] = u - (float)u0; fv[j] = v - (float)v0;
        i00[j] = v0*W_ + u0;
        i10[j] = i00[j] + W_;
    }

    // stage B: issue ALL 48 gathers back-to-back (max MLP)
    float za[4], zb[4], zc[4], zd[4];
    float xa[4], xb[4], xc[4], xd4[4];
    float ya[4], yb[4], yc[4], yd[4];
#pragma unroll
    for (int j = 0; j < 4; j++) { za[j] = __ldg(zg  + i00[j]); zb[j] = __ldg(zg  + i00[j] + 1);
                                  zc[j] = __ldg(zg  + i10[j]); zd[j] = __ldg(zg  + i10[j] + 1); }
#pragma unroll
    for (int j = 0; j < 4; j++) { xa[j] = __ldg(zgx + i00[j]); xb[j] = __ldg(zgx + i00[j] + 1);
                                  xc[j] = __ldg(zgx + i10[j]); xd4[j] = __ldg(zgx + i10[j] + 1); }
#pragma unroll
    for (int j = 0; j < 4; j++) { ya[j] = __ldg(zgy + i00[j]); yb[j] = __ldg(zgy + i00[j] + 1);
                                  yc[j] = __ldg(zgy + i10[j]); yd[j] = __ldg(zgy + i10[j] + 1); }

    // stage C: consume
    float gxr[4], gyr[4], dhr[4];
    float icsum = 0.0f;
#pragma unroll
    for (int j = 0; j < 4; j++) {
        const float gu = 1.0f - fu[j], gv = 1.0f - fv[j];
        const float zs = (za[j]*gu + zb[j]*fu[j])*gv + (zc[j]*gu + zd[j]*fu[j])*fv[j];
        const float gx = (xa[j]*gu + xb[j]*fu[j])*gv + (xc[j]*gu + xd4[j]*fu[j])*fv[j];
        const float gy = (ya[j]*gu + yb[j]*fu[j])*gv + (yc[j]*gu + yd[j]*fu[j])*fv[j];
        const float nrm = sqrtf(gx*gx + gy*gy + 1.0f);
        const float inv = __fdividef(1.0f, nrm + 1e-8f);
        const float dh = (rpz[j] - zs) * inv;   // nz == inv
        const float ic = 0.5f * (1.0f + tanh_fast(dh * IC_SCALE));
        gxr[j] = gx; gyr[j] = gy; dhr[j] = dh;
        icsum += ic;
    }

    // coalesced float4 outputs: robot_points + in_contact
    {
        float4* rpo = reinterpret_cast<float4*>(out + OFF_RP + (size_t)b*3072) + 3*tid;
        rpo[0] = make_float4(rpx[0], rpy[0], rpz[0], rpx[1]);
        rpo[1] = make_float4(rpy[1], rpz[1], rpx[2], rpy[2]);
        rpo[2] = make_float4(rpz[2], rpx[3], rpy[3], rpz[3]);
        const float ic0 = 0.5f*(1.0f + tanh_fast(dhr[0]*IC_SCALE));
        const float ic1 = 0.5f*(1.0f + tanh_fast(dhr[1]*IC_SCALE));
        const float ic2 = 0.5f*(1.0f + tanh_fast(dhr[2]*IC_SCALE));
        const float ic3 = 0.5f*(1.0f + tanh_fast(dhr[3]*IC_SCALE));
        float4* ico = reinterpret_cast<float4*>(out + OFF_IC + (size_t)b*1024) + tid;
        *ico = make_float4(ic0, ic1, ic2, ic3);
    }

    {   // contact-count partials
        const float ws = warp_sum(icsum);
        if ((tid & 31) == 0) s_red[w] = ws;
    }
    __syncthreads();

    float nc = 0.0f;
#pragma unroll
    for (int w8 = 0; w8 < 8; w8++) nc += s_red[w8];
    nc = fmaxf(nc, 1.0f);
    const float inv_nc = __fdividef(1.0f, nc);
    const float kd = sqrtf(s_tm * K_STIFF * inv_nc);   // DAMPING_ALPHA*2 = 1

    // ------------------ Phase 2: forces ------------------
    const float gddx = s_gdd[0], gddy = s_gdd[1], gddz = s_gdd[2];
    const float ox = s_om[0], oy = s_om[1], oz = s_om[2];
    const float gc0 = s_gcog[0], gc1 = s_gcog[1], gc2 = s_gcog[2];
    const float xd0 = s_xd[0], xd1 = s_xd[1], xd2 = s_xd[2];
    const float thx = s_thr[w][0], thy = s_thr[w][1], thz = s_thr[w][2];

    float fsb[12], ffb[12];
    float asx=0.f, asy=0.f, asz=0.f, tqx=0.f, tqy=0.f, tqz=0.f;

#pragma unroll
    for (int j = 0; j < 4; j++) {
        const float gx = gxr[j], gy = gyr[j], dh = dhr[j];
        const float nrm = sqrtf(gx*gx + gy*gy + 1.0f);
        const float invn = __fdividef(1.0f, nrm + 1e-8f);
        const float nx = -gx*invn, ny = -gy*invn, nz = invn;
        const float ic = 0.5f * (1.0f + tanh_fast(dh * IC_SCALE));

        const float ccx = rpx[j] - gc0;
        const float ccy = rpy[j] - gc1;
        const float ccz = rpz[j] - gc2;
        const float vx = xd0 + oy*ccz - oz*ccy;
        const float vy = xd1 + oz*ccx - ox*ccz;
        const float vz = xd2 + ox*ccy - oy*ccx;
        const float xdn = vx*nx + vy*ny + vz*nz;
        const float coef = -(K_STIFF * (dh*ic) + kd * xdn) * ic * inv_nc;
        const float fsx = coef*nx, fsy = coef*ny, fsz = coef*nz;
        const float Nmag = fabsf(coef);       // |F_spring| since |n| == 1

        const float gdn = gddx*nx + gddy*ny + gddz*nz;
        float fwx = gddx - gdn*nx, fwy = gddy - gdn*ny, fwz = gddz - gdn*nz;
        {
            const float fn = sqrtf(fwx*fwx + fwy*fwy + fwz*fwz);
            const float iv = __fdividef(1.0f, fn + 1e-8f);
            fwx *= iv; fwy *= iv; fwz *= iv;
        }
        float ltx = fwy*nz - fwz*ny;
        float lty = fwz*nx - fwx*nz;
        float ltz = fwx*ny - fwy*nx;
        {
            const float ln = sqrtf(ltx*ltx + lty*lty + ltz*ltz);
            const float iv = __fdividef(1.0f, ln + 1e-8f);
            ltx *= iv; lty *= iv; ltz *= iv;
        }
        const float dvx = thx - vx;
        const float dvy = thy - vy;
        const float dvz = thz - vz;
        const float dvn = dvx*nx + dvy*ny + dvz*nz;
        const float tx = tanh_fast(dvx - dvn*nx);
        const float ty = tanh_fast(dvy - dvn*ny);
        const float tz = tanh_fast(dvz - dvn*nz);
        const float lon = tx*fwx + ty*fwy + tz*fwz;
        const float lat = tx*ltx + ty*lty + tz*ltz;
        const float c1 = K_LON * Nmag * lon;
        const float c2 = K_LAT * Nmag * lat;
        const float ffx = c1*fwx + c2*ltx;
        const float ffy = c1*fwy + c2*lty;
        const float ffz = c1*fwz + c2*ltz;

        const float ax = fsx + ffx, ay = fsy + ffy, az = fsz + ffz;
        asx += ax; asy += ay; asz += az;
        tqx += ccy*az - ccz*ay;
        tqy += ccz*ax - ccx*az;
        tqz += ccx*ay - ccy*ax;

        fsb[3*j+0] = fsx; fsb[3*j+1] = fsy; fsb[3*j+2] = fsz;
        ffb[3*j+0] = ffx; ffb[3*j+1] = ffy; ffb[3*j+2] = ffz;
    }

    // coalesced float4 outputs: F_spring, F_friction, thrust
    {
        float4* fso = reinterpret_cast<float4*>(out + OFF_FS + (size_t)b*3072) + 3*tid;
        fso[0] = make_float4(fsb[0], fsb[1], fsb[2],  fsb[3]);
        fso[1] = make_float4(fsb[4], fsb[5], fsb[6],  fsb[7]);
        fso[2] = make_float4(fsb[8], fsb[9], fsb[10], fsb[11]);
        float4* ffo = reinterpret_cast<float4*>(out + OFF_FF + (size_t)b*3072) + 3*tid;
        ffo[0] = make_float4(ffb[0], ffb[1], ffb[2],  ffb[3]);
        ffo[1] = make_float4(ffb[4], ffb[5], ffb[6],  ffb[7]);
        ffo[2] = make_float4(ffb[8], ffb[9], ffb[10], ffb[11]);
        float4* tho = reinterpret_cast<float4*>(out + OFF_THR + (size_t)b*3072) + 3*tid;
        tho[0] = make_float4(thx, thy, thz, thx);
        tho[1] = make_float4(thy, thz, thx, thy);
        tho[2] = make_float4(thz, thx, thy, thz);
    }

    {   // reduce 6 sums
        float r[6] = {asx, asy, asz, tqx, tqy, tqz};
#pragma unroll
        for (int j = 0; j < 6; j++) {
            const float ws = warp_sum(r[j]);
            if ((tid & 31) == 0) s_red[j*8 + w] = ws;
        }
    }
    __syncthreads();

    // ------------------ Phase 3: solve + integrate ------------------
    if (tid == 0) {
        float as0 = 0.f, as1 = 0.f, as2 = 0.f, t0 = 0.f, t1 = 0.f, t2 = 0.f;
#pragma unroll
        for (int w8 = 0; w8 < 8; w8++) {
            as0 += s_red[0*8 + w8]; as1 += s_red[1*8 + w8]; as2 += s_red[2*8 + w8];
            t0  += s_red[3*8 + w8]; t1  += s_red[4*8 + w8]; t2  += s_red[5*8 + w8];
        }
        const float tqcx = fminf(fmaxf(t0, -TORQUE_LIM), TORQUE_LIM);
        const float tqcy = fminf(fmaxf(t1, -TORQUE_LIM), TORQUE_LIM);
        const float tqcz = fminf(fmaxf(t2, -TORQUE_LIM), TORQUE_LIM);
        out[OFF_TQ + (size_t)b*3 + 0] = tqcx;
        out[OFF_TQ + (size_t)b*3 + 1] = tqcy;
        out[OFF_TQ + (size_t)b*3 + 2] = tqcz;

        const double a00=s_inertia[0], a01=s_inertia[1], a02=s_inertia[2];
        const double a10=s_inertia[3], a11=s_inertia[4], a12=s_inertia[5];
        const double a20=s_inertia[6], a21=s_inertia[7], a22=s_inertia[8];
        const double bx=tqcx, by=tqcy, bz=tqcz;
        const double c00 = a11*a22 - a12*a21;
        const double c01 = a10*a22 - a12*a20;
        const double c02 = a10*a21 - a11*a20;
        const double det = a00*c00 - a01*c01 + a02*c02;
        const double inv = 1.0/det;
        const double odx = (bx*c00 - a01*(by*a22 - a12*bz) + a02*(by*a21 - a11*bz)) * inv;
        const double ody = (a00*(by*a22 - a12*bz) - bx*c01 + a02*(a10*bz - by*a20)) * inv;
        const double odz = (a00*(a11*bz - by*a21) - a01*(a10*bz - by*a20) + bx*c02) * inv;
        const float odxf=(float)odx, odyf=(float)ody, odzf=(float)odz;
        out[OFF_OMD + (size_t)b*3 + 0] = odxf;
        out[OFF_OMD + (size_t)b*3 + 1] = odyf;
        out[OFF_OMD + (size_t)b*3 + 2] = odzf;

        const float itm = __fdividef(1.0f, s_tm);
        const float xddx = as0 * itm;
        const float xddy = as1 * itm;
        const float xddz = (as2 - s_tm*GRAVITY) * itm;
        out[OFF_XDD + (size_t)b*3 + 0] = xddx;
        out[OFF_XDD + (size_t)b*3 + 1] = xddy;
        out[OFF_XDD + (size_t)b*3 + 2] = xddz;

        const float nxd0 = s_xd[0] + xddx*DT;
        const float nxd1 = s_xd[1] + xddy*DT;
        const float nxd2 = s_xd[2] + xddz*DT;
        out[OFF_NXD + (size_t)b*3 + 0] = nxd0;
        out[OFF_NXD + (size_t)b*3 + 1] = nxd1;
        out[OFF_NXD + (size_t)b*3 + 2] = nxd2;
        out[OFF_NX + (size_t)b*3 + 0] = s_x[0] + nxd0*DT;
        out[OFF_NX + (size_t)b*3 + 1] = s_x[1] + nxd1*DT;
        out[OFF_NX + (size_t)b*3 + 2] = s_x[2] + nxd2*DT;

        const float no0 = s_om[0] + odxf*DT;
        const float no1 = s_om[1] + odyf*DT;
        const float no2 = s_om[2] + odzf*DT;
        out[OFF_NOM + (size_t)b*3 + 0] = no0;
        out[OFF_NOM + (size_t)b*3 + 1] = no1;
        out[OFF_NOM + (size_t)b*3 + 2] = no2;

        const float aw = q_in[b*4+0], axq = q_in[b*4+1], ayq = q_in[b*4+2], azq = q_in[b*4+3];
        const float h = 0.5f * DT;
        const float dqw = h * (-(axq*no0 + ayq*no1 + azq*no2));
        const float dqx = h * ( aw*no0 + ayq*no2 - azq*no1);
        const float dqy = h * ( aw*no1 - axq*no2 + azq*no0);
        const float dqz = h * ( aw*no2 + axq*no1 - ayq*no0);
        const float nqw = aw + dqw, nqx = axq + dqx, nqy = ayq + dqy, nqz = azq + dqz;
        const float qn = sqrtf(nqw*nqw + nqx*nqx + nqy*nqy + nqz*nqz);
        const float qi = __fdividef(1.0f, qn + 1e-8f);
        out[OFF_NQ + (size_t)b*4 + 0] = nqw*qi;
        out[OFF_NQ + (size_t)b*4 + 1] = nqx*qi;
        out[OFF_NQ + (size_t)b*4 + 2] = nqy*qi;
        out[OFF_NQ + (size_t)b*4 + 3] = nqz*qi;
    }
}

extern "C" void kernel_launch(void* const* d_in, const int* in_sizes, int n_in,
                              void* d_out, int out_size)
{
    phys_kernel<<<B_, NTHREADS>>>(
        (const float*)d_in[0],  (const float*)d_in[1],  (const float*)d_in[2],
        (const float*)d_in[3],  (const float*)d_in[4],  (const float*)d_in[5],
        (const float*)d_in[6],  (const float*)d_in[7],  (const float*)d_in[8],
        (const float*)d_in[9],  (const float*)d_in[10], (const float*)d_in[11],
        (const float*)d_in[12], (const float*)d_in[13], (const float*)d_in[14],
        (const float*)d_in[15], (float*)d_out);
}

// round 8
// speedup vs baseline: 1.5481x; 1.2841x over previous
#include <cuda_runtime.h>
#include <math.h>

#define B_    1024
#define D_    8
#define P_    128
#define NPTS  1024
#define H_    256
#define W_    256
#define NTHREADS 256

#define GRAVITY     9.8f
#define DT          0.01f
#define TORQUE_LIM  200.0f
#define K_STIFF     5000.0f
#define K_LON       0.5f
#define K_LAT       0.5f
#define BODY_MASS   40.0f
#define MAX_COORD   6.4f
#define IC_SCALE    (-57.73502691896258f)   /* -sqrt(3)/SIGMA */
#define UV_SCALE    19.921875f              /* (W-1)/(2*MAX_COORD) */

// output offsets (floats)
#define OFF_NX   0
#define OFF_NXD  3072
#define OFF_NQ   6144
#define OFF_NOM  10240
#define OFF_NTH  13312
#define OFF_XDD  21504
#define OFF_OMD  24576
#define OFF_THD  27648
#define OFF_FS   35840
#define OFF_FF   3181568
#define OFF_IC   6327296
#define OFF_TQ   7375872
#define OFF_RP   7378944
#define OFF_THR  10524672

__device__ __forceinline__ float warp_sum(float v) {
#pragma unroll
    for (int o = 16; o; o >>= 1) v += __shfl_xor_sync(0xffffffffu, v, o);
    return v;
}

__device__ __forceinline__ float tanh_fast(float x) {
    float y;
    asm("tanh.approx.f32 %0, %1;" : "=f"(y) : "f"(x));
    return y;
}

__global__ __launch_bounds__(NTHREADS, 4)
void phys_kernel(const float* __restrict__ x_in,
                 const float* __restrict__ xd_in,
                 const float* __restrict__ q_in,
                 const float* __restrict__ om_in,
                 const float* __restrict__ th_in,
                 const float* __restrict__ ctrl_in,
                 const float* __restrict__ zg_in,
                 const float* __restrict__ zgg_in,
                 const float* __restrict__ jp_in,
                 const float* __restrict__ jlp_in,
                 const float* __restrict__ jlc_in,
                 const float* __restrict__ dpi_in,
                 const float* __restrict__ dpm_in,
                 const float* __restrict__ bcog_in,
                 const float* __restrict__ binert_in,
                 const float* __restrict__ ddir_in,
                 float* __restrict__ out)
{
    const int b   = blockIdx.x;
    const int tid = threadIdx.x;

    __shared__ float s_rp[3][NPTS];
    __shared__ float s_n [3][NPTS];
    __shared__ float s_dh[NPTS], s_ic[NPTS];

    __shared__ float sR[9];
    __shared__ float s_c[D_], s_sn[D_];
    __shared__ float s_jp[D_][3];
    __shared__ float s_cogl[D_][3];
    __shared__ float s_rotI[D_][9];
    __shared__ float s_tl[D_][3];
    __shared__ float s_thr[D_][3];
    __shared__ float s_Iov[9], s_M9[9];
    __shared__ float s_gcog[3], s_gdd[3], s_inertia[9];
    __shared__ float s_x[3], s_xd[3], s_om[3];
    __shared__ float s_tm;
    __shared__ float s_red[48];

    // ------------------ Phase 0a: per-part prep ------------------
    if (tid < D_) {
        const int d = tid;
        const float th = th_in[b * D_ + d];
        const float c = cosf(th), s = sinf(th);
        s_c[d] = c; s_sn[d] = s;
        const float jpx = jp_in[d*3+0], jpy = jp_in[d*3+1], jpz = jp_in[d*3+2];
        s_jp[d][0] = jpx; s_jp[d][1] = jpy; s_jp[d][2] = jpz;
        const float lx = jlc_in[d*3+0], ly = jlc_in[d*3+1], lz = jlc_in[d*3+2];
        s_cogl[d][0] =  c*lx + s*lz + jpx;
        s_cogl[d][1] =  ly + jpy;
        s_cogl[d][2] = -s*lx + c*lz + jpz;
        float I9[9];
#pragma unroll
        for (int k = 0; k < 9; k++) I9[k] = dpi_in[d*9 + k];
        float M[9];
        M[0] =  c*I9[0] + s*I9[6];  M[1] =  c*I9[1] + s*I9[7];  M[2] =  c*I9[2] + s*I9[8];
        M[3] =  I9[3];              M[4] =  I9[4];              M[5] =  I9[5];
        M[6] = -s*I9[0] + c*I9[6];  M[7] = -s*I9[1] + c*I9[7];  M[8] = -s*I9[2] + c*I9[8];
#pragma unroll
        for (int r = 0; r < 3; r++) {
            s_rotI[d][r*3+0] =  M[r*3+0]*c + M[r*3+2]*s;
            s_rotI[d][r*3+1] =  M[r*3+1];
            s_rotI[d][r*3+2] = -M[r*3+0]*s + M[r*3+2]*c;
        }
        const float dx = ddir_in[0], dy = ddir_in[1], dz = ddir_in[2];
        const float vc = ctrl_in[b*2*D_ + d];
        s_tl[d][0] = ( c*dx + s*dz) * vc;
        s_tl[d][1] = ( dy          ) * vc;
        s_tl[d][2] = (-s*dx + c*dz) * vc;
        float td = ctrl_in[b*2*D_ + D_ + d];
        td = fminf(fmaxf(td, -0.5f), 0.5f);
        out[OFF_THD + (size_t)b*D_ + d] = td;
        float nth = th + td * DT;
        out[OFF_NTH + (size_t)b*D_ + d] = fminf(fmaxf(nth, -1.0f), 1.0f);
    }
    if (tid == 8) {
        const float qw = q_in[b*4+0], qx = q_in[b*4+1], qy = q_in[b*4+2], qz = q_in[b*4+3];
        sR[0] = 1.0f - 2.0f*(qy*qy + qz*qz);
        sR[1] = 2.0f*(qx*qy - qw*qz);
        sR[2] = 2.0f*(qx*qz + qw*qy);
        sR[3] = 2.0f*(qx*qy + qw*qz);
        sR[4] = 1.0f - 2.0f*(qx*qx + qz*qz);
        sR[5] = 2.0f*(qy*qz - qw*qx);
        sR[6] = 2.0f*(qx*qz - qw*qy);
        sR[7] = 2.0f*(qy*qz + qw*qx);
        sR[8] = 1.0f - 2.0f*(qx*qx + qy*qy);
    }
    if (tid == 9) {
#pragma unroll
        for (int k = 0; k < 3; k++) {
            s_x[k]  = x_in[b*3+k];
            s_xd[k] = xd_in[b*3+k];
            s_om[k] = om_in[b*3+k];
        }
    }
    __syncthreads();

    // ------------------ Phase 0b: warp 0 only, overlapped with phase 1 ----
    if (tid < 32) {
        float m[D_];
        float tm = BODY_MASS;
#pragma unroll
        for (int d = 0; d < D_; d++) { m[d] = dpm_in[d]; tm += m[d]; }
        float cg0 = 0.f, cg1 = 0.f, cg2 = 0.f;
#pragma unroll
        for (int d = 0; d < D_; d++) {
            cg0 += s_cogl[d][0] * m[d];
            cg1 += s_cogl[d][1] * m[d];
            cg2 += s_cogl[d][2] * m[d];
        }
        const float bc0 = bcog_in[0], bc1 = bcog_in[1], bc2 = bcog_in[2];
        const float itm = 1.0f / tm;
        cg0 = (cg0 + BODY_MASS*bc0) * itm;
        cg1 = (cg1 + BODY_MASS*bc1) * itm;
        cg2 = (cg2 + BODY_MASS*bc2) * itm;

        if (tid < 24) {
            const int d = tid / 3, k = tid - 3*(tid/3);
            s_thr[d][k] = sR[k*3+0]*s_tl[d][0] + sR[k*3+1]*s_tl[d][1] + sR[k*3+2]*s_tl[d][2];
        }
        if (tid < 9) {
            const int r = tid / 3, c = tid - 3*(tid/3);
            float Iv = binert_in[tid];
#pragma unroll
            for (int d = 0; d < D_; d++) {
                const float ddx = s_cogl[d][0]-cg0, ddy = s_cogl[d][1]-cg1, ddz = s_cogl[d][2]-cg2;
                const float s2 = ddx*ddx + ddy*ddy + ddz*ddz;
                const float er = (r==0)?ddx:(r==1)?ddy:ddz;
                const float ec = (c==0)?ddx:(c==1)?ddy:ddz;
                Iv += s_rotI[d][tid] + m[d]*(((r==c)?s2:0.0f) - er*ec);
            }
            {
                const float ddx = bc0-cg0, ddy = bc1-cg1, ddz = bc2-cg2;
                const float s2 = ddx*ddx + ddy*ddy + ddz*ddz;
                const float er = (r==0)?ddx:(r==1)?ddy:ddz;
                const float ec = (c==0)?ddx:(c==1)?ddy:ddz;
                Iv += BODY_MASS*(((r==c)?s2:0.0f) - er*ec);
            }
            s_Iov[tid] = Iv;
        }
        if (tid >= 9 && tid < 12) {
            const int k = tid - 9;
            s_gcog[k] = sR[k*3+0]*cg0 + sR[k*3+1]*cg1 + sR[k*3+2]*cg2 + s_x[k];
        }
        if (tid >= 12 && tid < 15) {
            const int k = tid - 12;
            s_gdd[k] = sR[k*3+0]*ddir_in[0] + sR[k*3+1]*ddir_in[1] + sR[k*3+2]*ddir_in[2];
        }
        if (tid == 15) s_tm = tm;
        __syncwarp();
        if (tid < 9) {
            const int r = tid / 3, c = tid - 3*(tid/3);
            s_M9[tid] = sR[r*3+0]*s_Iov[c] + sR[r*3+1]*s_Iov[3+c] + sR[r*3+2]*s_Iov[6+c];
        }
        __syncwarp();
        if (tid < 9) {
            const int r = tid / 3, c = tid - 3*(tid/3);
            s_inertia[tid] = s_M9[r*3+0]*sR[c*3+0] + s_M9[r*3+1]*sR[c*3+1] + s_M9[r*3+2]*sR[c*3+2];
        }
    }

    // ------------------ Phase 1: points, terrain sample ------------------
    const float* __restrict__ zg  = zg_in  + (size_t)b * (H_*W_);
    const float* __restrict__ zgx = zgg_in + (size_t)b * (2*H_*W_);
    const float* __restrict__ zgy = zgx + H_*W_;

    float icsum = 0.0f;
#pragma unroll
    for (int k = 0; k < NPTS/NTHREADS; k++) {
        const int i = tid + k * NTHREADS;
        const int d = i >> 7;
        const float* jl = jlp_in + (size_t)i * 3;
        const float jx = jl[0], jy = jl[1], jz = jl[2];
        const float c = s_c[d], s = s_sn[d];
        const float plx =  c*jx + s*jz + s_jp[d][0];
        const float ply =  jy          + s_jp[d][1];
        const float plz = -s*jx + c*jz + s_jp[d][2];
        const float rx = sR[0]*plx + sR[1]*ply + sR[2]*plz + s_x[0];
        const float ry = sR[3]*plx + sR[4]*ply + sR[5]*plz + s_x[1];
        const float rz = sR[6]*plx + sR[7]*ply + sR[8]*plz + s_x[2];
        s_rp[0][i] = rx; s_rp[1][i] = ry; s_rp[2][i] = rz;

        const size_t p3 = ((size_t)b * NPTS + i) * 3;
        out[OFF_RP + p3 + 0] = rx;
        out[OFF_RP + p3 + 1] = ry;
        out[OFF_RP + p3 + 2] = rz;

        float u = (rx + MAX_COORD) * UV_SCALE;
        float v = (ry + MAX_COORD) * UV_SCALE;
        u = fminf(fmaxf(u, 0.0f), (float)(W_-1) - 1e-5f);
        v = fminf(fmaxf(v, 0.0f), (float)(H_-1) - 1e-5f);
        const int u0 = (int)floorf(u), v0 = (int)floorf(v);
        const float fu = u - (float)u0, fv = v - (float)v0;
        const int i00 = v0*W_ + u0;
        const int i10 = i00 + W_;

        const float z00 = __ldg(zg + i00),  z01 = __ldg(zg + i00 + 1);
        const float z10 = __ldg(zg + i10),  z11 = __ldg(zg + i10 + 1);
        const float x00 = __ldg(zgx + i00), x01 = __ldg(zgx + i00 + 1);
        const float x10 = __ldg(zgx + i10), x11 = __ldg(zgx + i10 + 1);
        const float y00 = __ldg(zgy + i00), y01 = __ldg(zgy + i00 + 1);
        const float y10 = __ldg(zgy + i10), y11 = __ldg(zgy + i10 + 1);

        const float gu = 1.0f - fu, gv = 1.0f - fv;
        const float zs = (z00*gu + z01*fu)*gv + (z10*gu + z11*fu)*fv;
        const float gx = (x00*gu + x01*fu)*gv + (x10*gu + x11*fu)*fv;
        const float gy = (y00*gu + y01*fu)*gv + (y10*gu + y11*fu)*fv;

        // 1/(sqrt(ss)+1e-8) ≈ rsqrt(ss + 1e-16)  (rel diff ~1e-8)
        const float inv = rsqrtf(gx*gx + gy*gy + 1.0f + 1e-16f);
        const float nx = -gx*inv, ny = -gy*inv, nz = inv;
        const float dh = (rz - zs) * nz;
        const float ic = 0.5f * (1.0f + tanh_fast(dh * IC_SCALE));

        s_n[0][i] = nx; s_n[1][i] = ny; s_n[2][i] = nz;
        s_dh[i] = dh; s_ic[i] = ic;
        icsum += ic;
        out[OFF_IC + (size_t)b*NPTS + i] = ic;
    }

    {   // contact-count partials
        const float ws = warp_sum(icsum);
        const int warp = tid >> 5, lane = tid & 31;
        if (lane == 0) s_red[warp] = ws;
    }
    __syncthreads();

    // all threads compute nc redundantly (one barrier total)
    float nc = 0.0f;
#pragma unroll
    for (int w8 = 0; w8 < 8; w8++) nc += s_red[w8];
    nc = fmaxf(nc, 1.0f);
    const float inv_nc = __fdividef(1.0f, nc);
    const float kd = sqrtf(s_tm * K_STIFF * inv_nc);   // DAMPING_ALPHA*2 = 1

    // ------------------ Phase 2: forces ------------------
    const float gddx = s_gdd[0], gddy = s_gdd[1], gddz = s_gdd[2];
    const float ox = s_om[0], oy = s_om[1], oz = s_om[2];
    const float gc0 = s_gcog[0], gc1 = s_gcog[1], gc2 = s_gcog[2];
    const float xd0 = s_xd[0], xd1 = s_xd[1], xd2 = s_xd[2];
    float asx=0.f, asy=0.f, asz=0.f, tqx=0.f, tqy=0.f, tqz=0.f;

#pragma unroll
    for (int k = 0; k < NPTS/NTHREADS; k++) {
        const int i = tid + k * NTHREADS;
        const int d = i >> 7;
        const float nx = s_n[0][i], ny = s_n[1][i], nz = s_n[2][i];
        const float dh = s_dh[i], ic = s_ic[i];
        const float ccx = s_rp[0][i] - gc0;
        const float ccy = s_rp[1][i] - gc1;
        const float ccz = s_rp[2][i] - gc2;
        const float vx = xd0 + oy*ccz - oz*ccy;
        const float vy = xd1 + oz*ccx - ox*ccz;
        const float vz = xd2 + ox*ccy - oy*ccx;
        const float xdn = vx*nx + vy*ny + vz*nz;
        const float coef = -(K_STIFF * (dh*ic) + kd * xdn) * ic * inv_nc;
        const float fsx = coef*nx, fsy = coef*ny, fsz = coef*nz;
        const float Nmag = fabsf(coef);       // ||coef * n||, |n| == 1

        const float gdn = gddx*nx + gddy*ny + gddz*nz;
        float fwx = gddx - gdn*nx, fwy = gddy - gdn*ny, fwz = gddz - gdn*nz;
        {
            const float iv = rsqrtf(fwx*fwx + fwy*fwy + fwz*fwz + 1e-16f);
            fwx *= iv; fwy *= iv; fwz *= iv;
        }
        float ltx = fwy*nz - fwz*ny;
        float lty = fwz*nx - fwx*nz;
        float ltz = fwx*ny - fwy*nx;
        {
            const float iv = rsqrtf(ltx*ltx + lty*lty + ltz*ltz + 1e-16f);
            ltx *= iv; lty *= iv; ltz *= iv;
        }
        const float thx = s_thr[d][0], thy = s_thr[d][1], thz = s_thr[d][2];
        const float dvx = thx - vx;
        const float dvy = thy - vy;
        const float dvz = thz - vz;
        const float dvn = dvx*nx + dvy*ny + dvz*nz;
        const float tx = tanh_fast(dvx - dvn*nx);
        const float ty = tanh_fast(dvy - dvn*ny);
        const float tz = tanh_fast(dvz - dvn*nz);
        const float lon = tx*fwx + ty*fwy + tz*fwz;
        const float lat = tx*ltx + ty*lty + tz*ltz;
        const float c1 = K_LON * Nmag * lon;
        const float c2 = K_LAT * Nmag * lat;
        const float ffx = c1*fwx + c2*ltx;
        const float ffy = c1*fwy + c2*lty;
        const float ffz = c1*fwz + c2*ltz;

        const float ax = fsx + ffx, ay = fsy + ffy, az = fsz + ffz;
        asx += ax; asy += ay; asz += az;
        tqx += ccy*az - ccz*ay;
        tqy += ccz*ax - ccx*az;
        tqz += ccx*ay - ccy*ax;

        const size_t p3 = ((size_t)b * NPTS + i) * 3;
        out[OFF_FS + p3 + 0] = fsx;
        out[OFF_FS + p3 + 1] = fsy;
        out[OFF_FS + p3 + 2] = fsz;
        out[OFF_FF + p3 + 0] = ffx;
        out[OFF_FF + p3 + 1] = ffy;
        out[OFF_FF + p3 + 2] = ffz;
        out[OFF_THR + p3 + 0] = thx;
        out[OFF_THR + p3 + 1] = thy;
        out[OFF_THR + p3 + 2] = thz;
    }

    {   // reduce 6 sums
        float r[6] = {asx, asy, asz, tqx, tqy, tqz};
        const int warp = tid >> 5, lane = tid & 31;
#pragma unroll
        for (int j = 0; j < 6; j++) {
            const float ws = warp_sum(r[j]);
            if (lane == 0) s_red[j*8 + warp] = ws;
        }
    }
    __syncthreads();

    // ------------------ Phase 3: solve + integrate ------------------
    if (tid == 0) {
        float as0 = 0.f, as1 = 0.f, as2 = 0.f, t0 = 0.f, t1 = 0.f, t2 = 0.f;
#pragma unroll
        for (int w8 = 0; w8 < 8; w8++) {
            as0 += s_red[0*8 + w8]; as1 += s_red[1*8 + w8]; as2 += s_red[2*8 + w8];
            t0  += s_red[3*8 + w8]; t1  += s_red[4*8 + w8]; t2  += s_red[5*8 + w8];
        }
        const float tqcx = fminf(fmaxf(t0, -TORQUE_LIM), TORQUE_LIM);
        const float tqcy = fminf(fmaxf(t1, -TORQUE_LIM), TORQUE_LIM);
        const float tqcz = fminf(fmaxf(t2, -TORQUE_LIM), TORQUE_LIM);
        out[OFF_TQ + (size_t)b*3 + 0] = tqcx;
        out[OFF_TQ + (size_t)b*3 + 1] = tqcy;
        out[OFF_TQ + (size_t)b*3 + 2] = tqcz;

        const double a00=s_inertia[0], a01=s_inertia[1], a02=s_inertia[2];
        const double a10=s_inertia[3], a11=s_inertia[4], a12=s_inertia[5];
        const double a20=s_inertia[6], a21=s_inertia[7], a22=s_inertia[8];
        const double bx=tqcx, by=tqcy, bz=tqcz;
        const double c00 = a11*a22 - a12*a21;
        const double c01 = a10*a22 - a12*a20;
        const double c02 = a10*a21 - a11*a20;
        const double det = a00*c00 - a01*c01 + a02*c02;
        const double inv = 1.0/det;
        const double odx = (bx*c00 - a01*(by*a22 - a12*bz) + a02*(by*a21 - a11*bz)) * inv;
        const double ody = (a00*(by*a22 - a12*bz) - bx*c01 + a02*(a10*bz - by*a20)) * inv;
        const double odz = (a00*(a11*bz - by*a21) - a01*(a10*bz - by*a20) + bx*c02) * inv;
        const float odxf=(float)odx, odyf=(float)ody, odzf=(float)odz;
        out[OFF_OMD + (size_t)b*3 + 0] = odxf;
        out[OFF_OMD + (size_t)b*3 + 1] = odyf;
        out[OFF_OMD + (size_t)b*3 + 2] = odzf;

        const float itm = __fdividef(1.0f, s_tm);
        const float xddx = as0 * itm;
        const float xddy = as1 * itm;
        const float xddz = (as2 - s_tm*GRAVITY) * itm;
        out[OFF_XDD + (size_t)b*3 + 0] = xddx;
        out[OFF_XDD + (size_t)b*3 + 1] = xddy;
        out[OFF_XDD + (size_t)b*3 + 2] = xddz;

        const float nxd0 = s_xd[0] + xddx*DT;
        const float nxd1 = s_xd[1] + xddy*DT;
        const float nxd2 = s_xd[2] + xddz*DT;
        out[OFF_NXD + (size_t)b*3 + 0] = nxd0;
        out[OFF_NXD + (size_t)b*3 + 1] = nxd1;
        out[OFF_NXD + (size_t)b*3 + 2] = nxd2;
        out[OFF_NX + (size_t)b*3 + 0] = s_x[0] + nxd0*DT;
        out[OFF_NX + (size_t)b*3 + 1] = s_x[1] + nxd1*DT;
        out[OFF_NX + (size_t)b*3 + 2] = s_x[2] + nxd2*DT;

        const float no0 = s_om[0] + odxf*DT;
        const float no1 = s_om[1] + odyf*DT;
        const float no2 = s_om[2] + odzf*DT;
        out[OFF_NOM + (size_t)b*3 + 0] = no0;
        out[OFF_NOM + (size_t)b*3 + 1] = no1;
        out[OFF_NOM + (size_t)b*3 + 2] = no2;

        const float aw = q_in[b*4+0], axq = q_in[b*4+1], ayq = q_in[b*4+2], azq = q_in[b*4+3];
        const float h = 0.5f * DT;
        const float dqw = h * (-(axq*no0 + ayq*no1 + azq*no2));
        const float dqx = h * ( aw*no0 + ayq*no2 - azq*no1);
        const float dqy = h * ( aw*no1 - axq*no2 + azq*no0);
        const float dqz = h * ( aw*no2 + axq*no1 - ayq*no0);
        const float nqw = aw + dqw, nqx = axq + dqx, nqy = ayq + dqy, nqz = azq + dqz;
        const float qn = sqrtf(nqw*nqw + nqx*nqx + nqy*nqy + nqz*nqz);
        const float qi = __fdividef(1.0f, qn + 1e-8f);
        out[OFF_NQ + (size_t)b*4 + 0] = nqw*qi;
        out[OFF_NQ + (size_t)b*4 + 1] = nqx*qi;
        out[OFF_NQ + (size_t)b*4 + 2] = nqy*qi;
        out[OFF_NQ + (size_t)b*4 + 3] = nqz*qi;
    }
}

extern "C" void kernel_launch(void* const* d_in, const int* in_sizes, int n_in,
                              void* d_out, int out_size)
{
    phys_kernel<<<B_, NTHREADS>>>(
        (const float*)d_in[0],  (const float*)d_in[1],  (const float*)d_in[2],
        (const float*)d_in[3],  (const float*)d_in[4],  (const float*)d_in[5],
        (const float*)d_in[6],  (const float*)d_in[7],  (const float*)d_in[8],
        (const float*)d_in[9],  (const float*)d_in[10], (const float*)d_in[11],
        (const float*)d_in[12], (const float*)d_in[13], (const float*)d_in[14],
        (const float*)d_in[15], (float*)d_out);
}

// round 9
// speedup vs baseline: 1.7807x; 1.1502x over previous
#include <cuda_runtime.h>
#include <math.h>

#define B_    1024
#define D_    8
#define P_    128
#define NPTS  1024
#define H_    256
#define W_    256
#define NTHREADS 256

#define GRAVITY     9.8f
#define DT          0.01f
#define TORQUE_LIM  200.0f
#define K_STIFF     5000.0f
#define K_LON       0.5f
#define K_LAT       0.5f
#define BODY_MASS   40.0f
#define MAX_COORD   6.4f
#define IC_SCALE    (-57.73502691896258f)   /* -sqrt(3)/SIGMA */
#define UV_SCALE    19.921875f              /* (W-1)/(2*MAX_COORD) */

// output offsets (floats)
#define OFF_NX   0
#define OFF_NXD  3072
#define OFF_NQ   6144
#define OFF_NOM  10240
#define OFF_NTH  13312
#define OFF_XDD  21504
#define OFF_OMD  24576
#define OFF_THD  27648
#define OFF_FS   35840
#define OFF_FF   3181568
#define OFF_IC   6327296
#define OFF_TQ   7375872
#define OFF_RP   7378944
#define OFF_THR  10524672

__device__ __forceinline__ float warp_sum(float v) {
#pragma unroll
    for (int o = 16; o; o >>= 1) v += __shfl_xor_sync(0xffffffffu, v, o);
    return v;
}

__device__ __forceinline__ float tanh_fast(float x) {
    float y;
    asm("tanh.approx.f32 %0, %1;" : "=f"(y) : "f"(x));
    return y;
}

__global__ __launch_bounds__(NTHREADS, 4)
void phys_kernel(const float* __restrict__ x_in,
                 const float* __restrict__ xd_in,
                 const float* __restrict__ q_in,
                 const float* __restrict__ om_in,
                 const float* __restrict__ th_in,
                 const float* __restrict__ ctrl_in,
                 const float* __restrict__ zg_in,
                 const float* __restrict__ zgg_in,
                 const float* __restrict__ jp_in,
                 const float* __restrict__ jlp_in,
                 const float* __restrict__ jlc_in,
                 const float* __restrict__ dpi_in,
                 const float* __restrict__ dpm_in,
                 const float* __restrict__ bcog_in,
                 const float* __restrict__ binert_in,
                 const float* __restrict__ ddir_in,
                 float* __restrict__ out)
{
    const int b   = blockIdx.x;
    const int tid = threadIdx.x;

    // minimal per-point staging (24 KB): rp(3), gx, gy, dh
    __shared__ float s_rp[3][NPTS];
    __shared__ float s_gx[NPTS], s_gy[NPTS], s_dh[NPTS];

    __shared__ float sR[9];
    __shared__ float s_c[D_], s_sn[D_];
    __shared__ float s_jp[D_][3];
    __shared__ float s_cogl[D_][3];
    __shared__ float s_rotI[D_][9];
    __shared__ float s_tl[D_][3];
    __shared__ float s_thr[D_][3];
    __shared__ float s_Iov[9], s_M9[9];
    __shared__ float s_gcog[3], s_gdd[3], s_inertia[9];
    __shared__ float s_x[3], s_xd[3], s_om[3];
    __shared__ float s_tm;
    __shared__ float s_red[48];

    // ------------------ Phase 0a: per-part prep ------------------
    if (tid < D_) {
        const int d = tid;
        const float th = th_in[b * D_ + d];
        const float c = cosf(th), s = sinf(th);
        s_c[d] = c; s_sn[d] = s;
        const float jpx = jp_in[d*3+0], jpy = jp_in[d*3+1], jpz = jp_in[d*3+2];
        s_jp[d][0] = jpx; s_jp[d][1] = jpy; s_jp[d][2] = jpz;
        const float lx = jlc_in[d*3+0], ly = jlc_in[d*3+1], lz = jlc_in[d*3+2];
        s_cogl[d][0] =  c*lx + s*lz + jpx;
        s_cogl[d][1] =  ly + jpy;
        s_cogl[d][2] = -s*lx + c*lz + jpz;
        float I9[9];
#pragma unroll
        for (int k = 0; k < 9; k++) I9[k] = dpi_in[d*9 + k];
        float M[9];
        M[0] =  c*I9[0] + s*I9[6];  M[1] =  c*I9[1] + s*I9[7];  M[2] =  c*I9[2] + s*I9[8];
        M[3] =  I9[3];              M[4] =  I9[4];              M[5] =  I9[5];
        M[6] = -s*I9[0] + c*I9[6];  M[7] = -s*I9[1] + c*I9[7];  M[8] = -s*I9[2] + c*I9[8];
#pragma unroll
        for (int r = 0; r < 3; r++) {
            s_rotI[d][r*3+0] =  M[r*3+0]*c + M[r*3+2]*s;
            s_rotI[d][r*3+1] =  M[r*3+1];
            s_rotI[d][r*3+2] = -M[r*3+0]*s + M[r*3+2]*c;
        }
        const float dx = ddir_in[0], dy = ddir_in[1], dz = ddir_in[2];
        const float vc = ctrl_in[b*2*D_ + d];
        s_tl[d][0] = ( c*dx + s*dz) * vc;
        s_tl[d][1] = ( dy          ) * vc;
        s_tl[d][2] = (-s*dx + c*dz) * vc;
        float td = ctrl_in[b*2*D_ + D_ + d];
        td = fminf(fmaxf(td, -0.5f), 0.5f);
        out[OFF_THD + (size_t)b*D_ + d] = td;
        float nth = th + td * DT;
        out[OFF_NTH + (size_t)b*D_ + d] = fminf(fmaxf(nth, -1.0f), 1.0f);
    }
    if (tid == 8) {
        const float qw = q_in[b*4+0], qx = q_in[b*4+1], qy = q_in[b*4+2], qz = q_in[b*4+3];
        sR[0] = 1.0f - 2.0f*(qy*qy + qz*qz);
        sR[1] = 2.0f*(qx*qy - qw*qz);
        sR[2] = 2.0f*(qx*qz + qw*qy);
        sR[3] = 2.0f*(qx*qy + qw*qz);
        sR[4] = 1.0f - 2.0f*(qx*qx + qz*qz);
        sR[5] = 2.0f*(qy*qz - qw*qx);
        sR[6] = 2.0f*(qx*qz - qw*qy);
        sR[7] = 2.0f*(qy*qz + qw*qx);
        sR[8] = 1.0f - 2.0f*(qx*qx + qy*qy);
    }
    if (tid == 9) {
#pragma unroll
        for (int k = 0; k < 3; k++) {
            s_x[k]  = x_in[b*3+k];
            s_xd[k] = xd_in[b*3+k];
            s_om[k] = om_in[b*3+k];
        }
    }
    __syncthreads();

    // ------------------ Phase 0b: warp 0 only, overlapped with phase 1 ----
    if (tid < 32) {
        float m[D_];
        float tm = BODY_MASS;
#pragma unroll
        for (int d = 0; d < D_; d++) { m[d] = dpm_in[d]; tm += m[d]; }
        float cg0 = 0.f, cg1 = 0.f, cg2 = 0.f;
#pragma unroll
        for (int d = 0; d < D_; d++) {
            cg0 += s_cogl[d][0] * m[d];
            cg1 += s_cogl[d][1] * m[d];
            cg2 += s_cogl[d][2] * m[d];
        }
        const float bc0 = bcog_in[0], bc1 = bcog_in[1], bc2 = bcog_in[2];
        const float itm = 1.0f / tm;
        cg0 = (cg0 + BODY_MASS*bc0) * itm;
        cg1 = (cg1 + BODY_MASS*bc1) * itm;
        cg2 = (cg2 + BODY_MASS*bc2) * itm;

        if (tid < 24) {
            const int d = tid / 3, k = tid - 3*(tid/3);
            s_thr[d][k] = sR[k*3+0]*s_tl[d][0] + sR[k*3+1]*s_tl[d][1] + sR[k*3+2]*s_tl[d][2];
        }
        if (tid < 9) {
            const int r = tid / 3, c = tid - 3*(tid/3);
            float Iv = binert_in[tid];
#pragma unroll
            for (int d = 0; d < D_; d++) {
                const float ddx = s_cogl[d][0]-cg0, ddy = s_cogl[d][1]-cg1, ddz = s_cogl[d][2]-cg2;
                const float s2 = ddx*ddx + ddy*ddy + ddz*ddz;
                const float er = (r==0)?ddx:(r==1)?ddy:ddz;
                const float ec = (c==0)?ddx:(c==1)?ddy:ddz;
                Iv += s_rotI[d][tid] + m[d]*(((r==c)?s2:0.0f) - er*ec);
            }
            {
                const float ddx = bc0-cg0, ddy = bc1-cg1, ddz = bc2-cg2;
                const float s2 = ddx*ddx + ddy*ddy + ddz*ddz;
                const float er = (r==0)?ddx:(r==1)?ddy:ddz;
                const float ec = (c==0)?ddx:(c==1)?ddy:ddz;
                Iv += BODY_MASS*(((r==c)?s2:0.0f) - er*ec);
            }
            s_Iov[tid] = Iv;
        }
        if (tid >= 9 && tid < 12) {
            const int k = tid - 9;
            s_gcog[k] = sR[k*3+0]*cg0 + sR[k*3+1]*cg1 + sR[k*3+2]*cg2 + s_x[k];
        }
        if (tid >= 12 && tid < 15) {
            const int k = tid - 12;
            s_gdd[k] = sR[k*3+0]*ddir_in[0] + sR[k*3+1]*ddir_in[1] + sR[k*3+2]*ddir_in[2];
        }
        if (tid == 15) s_tm = tm;
        __syncwarp();
        if (tid < 9) {
            const int r = tid / 3, c = tid - 3*(tid/3);
            s_M9[tid] = sR[r*3+0]*s_Iov[c] + sR[r*3+1]*s_Iov[3+c] + sR[r*3+2]*s_Iov[6+c];
        }
        __syncwarp();
        if (tid < 9) {
            const int r = tid / 3, c = tid - 3*(tid/3);
            s_inertia[tid] = s_M9[r*3+0]*sR[c*3+0] + s_M9[r*3+1]*sR[c*3+1] + s_M9[r*3+2]*sR[c*3+2];
        }
    }

    // ------------------ Phase 1: points, terrain sample ------------------
    const float* __restrict__ zg  = zg_in  + (size_t)b * (H_*W_);
    const float* __restrict__ zgx = zgg_in + (size_t)b * (2*H_*W_);
    const float* __restrict__ zgy = zgx + H_*W_;

    float icsum = 0.0f;
#pragma unroll
    for (int k = 0; k < NPTS/NTHREADS; k++) {
        const int i = tid + k * NTHREADS;
        const int d = i >> 7;
        const float* jl = jlp_in + (size_t)i * 3;
        const float jx = jl[0], jy = jl[1], jz = jl[2];
        const float c = s_c[d], s = s_sn[d];
        const float plx =  c*jx + s*jz + s_jp[d][0];
        const float ply =  jy          + s_jp[d][1];
        const float plz = -s*jx + c*jz + s_jp[d][2];
        const float rx = sR[0]*plx + sR[1]*ply + sR[2]*plz + s_x[0];
        const float ry = sR[3]*plx + sR[4]*ply + sR[5]*plz + s_x[1];
        const float rz = sR[6]*plx + sR[7]*ply + sR[8]*plz + s_x[2];
        s_rp[0][i] = rx; s_rp[1][i] = ry; s_rp[2][i] = rz;

        const size_t p3 = ((size_t)b * NPTS + i) * 3;
        out[OFF_RP + p3 + 0] = rx;
        out[OFF_RP + p3 + 1] = ry;
        out[OFF_RP + p3 + 2] = rz;

        float u = (rx + MAX_COORD) * UV_SCALE;
        float v = (ry + MAX_COORD) * UV_SCALE;
        u = fminf(fmaxf(u, 0.0f), (float)(W_-1) - 1e-5f);
        v = fminf(fmaxf(v, 0.0f), (float)(H_-1) - 1e-5f);
        const int u0 = (int)floorf(u), v0 = (int)floorf(v);
        const float fu = u - (float)u0, fv = v - (float)v0;
        const int i00 = v0*W_ + u0;
        const int i10 = i00 + W_;

        const float z00 = __ldg(zg + i00),  z01 = __ldg(zg + i00 + 1);
        const float z10 = __ldg(zg + i10),  z11 = __ldg(zg + i10 + 1);
        const float x00 = __ldg(zgx + i00), x01 = __ldg(zgx + i00 + 1);
        const float x10 = __ldg(zgx + i10), x11 = __ldg(zgx + i10 + 1);
        const float y00 = __ldg(zgy + i00), y01 = __ldg(zgy + i00 + 1);
        const float y10 = __ldg(zgy + i10), y11 = __ldg(zgy + i10 + 1);

        const float gu = 1.0f - fu, gv = 1.0f - fv;
        const float zs = (z00*gu + z01*fu)*gv + (z10*gu + z11*fu)*fv;
        const float gx = (x00*gu + x01*fu)*gv + (x10*gu + x11*fu)*fv;
        const float gy = (y00*gu + y01*fu)*gv + (y10*gu + y11*fu)*fv;

        // 1/(sqrt(ss)+1e-8) ≈ rsqrt(ss + 1e-16)  (rel diff ~1e-8)
        const float inv = rsqrtf(gx*gx + gy*gy + 1.0f + 1e-16f);
        const float dh = (rz - zs) * inv;           // nz == inv
        const float ic = 0.5f * (1.0f + tanh_fast(dh * IC_SCALE));

        s_gx[i] = gx; s_gy[i] = gy; s_dh[i] = dh;
        icsum += ic;
        out[OFF_IC + (size_t)b*NPTS + i] = ic;
    }

    {   // contact-count partials
        const float ws = warp_sum(icsum);
        const int warp = tid >> 5, lane = tid & 31;
        if (lane == 0) s_red[warp] = ws;
    }
    __syncthreads();

    // all threads compute nc redundantly (one barrier total)
    float nc = 0.0f;
#pragma unroll
    for (int w8 = 0; w8 < 8; w8++) nc += s_red[w8];
    nc = fmaxf(nc, 1.0f);
    const float inv_nc = __fdividef(1.0f, nc);
    const float kd = sqrtf(s_tm * K_STIFF * inv_nc);   // DAMPING_ALPHA*2 = 1

    // ------------------ Phase 2: forces ------------------
    const float gddx = s_gdd[0], gddy = s_gdd[1], gddz = s_gdd[2];
    const float ox = s_om[0], oy = s_om[1], oz = s_om[2];
    const float gc0 = s_gcog[0], gc1 = s_gcog[1], gc2 = s_gcog[2];
    const float xd0 = s_xd[0], xd1 = s_xd[1], xd2 = s_xd[2];
    float asx=0.f, asy=0.f, asz=0.f, tqx=0.f, tqy=0.f, tqz=0.f;

#pragma unroll
    for (int k = 0; k < NPTS/NTHREADS; k++) {
        const int i = tid + k * NTHREADS;
        const int d = i >> 7;
        // recompute n, ic from staged {gx, gy, dh}
        const float gx = s_gx[i], gy = s_gy[i], dh = s_dh[i];
        const float invn = rsqrtf(gx*gx + gy*gy + 1.0f + 1e-16f);
        const float nx = -gx*invn, ny = -gy*invn, nz = invn;
        const float ic = 0.5f * (1.0f + tanh_fast(dh * IC_SCALE));

        const float ccx = s_rp[0][i] - gc0;
        const float ccy = s_rp[1][i] - gc1;
        const float ccz = s_rp[2][i] - gc2;
        const float vx = xd0 + oy*ccz - oz*ccy;
        const float vy = xd1 + oz*ccx - ox*ccz;
        const float vz = xd2 + ox*ccy - oy*ccx;
        const float xdn = vx*nx + vy*ny + vz*nz;
        const float coef = -(K_STIFF * (dh*ic) + kd * xdn) * ic * inv_nc;
        const float fsx = coef*nx, fsy = coef*ny, fsz = coef*nz;
        const float Nmag = fabsf(coef);       // ||coef * n||, |n| == 1

        const float gdn = gddx*nx + gddy*ny + gddz*nz;
        float fwx = gddx - gdn*nx, fwy = gddy - gdn*ny, fwz = gddz - gdn*nz;
        {
            const float iv = rsqrtf(fwx*fwx + fwy*fwy + fwz*fwz + 1e-16f);
            fwx *= iv; fwy *= iv; fwz *= iv;
        }
        float ltx = fwy*nz - fwz*ny;
        float lty = fwz*nx - fwx*nz;
        float ltz = fwx*ny - fwy*nx;
        {
            const float iv = rsqrtf(ltx*ltx + lty*lty + ltz*ltz + 1e-16f);
            ltx *= iv; lty *= iv; ltz *= iv;
        }
        const float thx = s_thr[d][0], thy = s_thr[d][1], thz = s_thr[d][2];
        const float dvx = thx - vx;
        const float dvy = thy - vy;
        const float dvz = thz - vz;
        const float dvn = dvx*nx + dvy*ny + dvz*nz;
        const float tx = tanh_fast(dvx - dvn*nx);
        const float ty = tanh_fast(dvy - dvn*ny);
        const float tz = tanh_fast(dvz - dvn*nz);
        const float lon = tx*fwx + ty*fwy + tz*fwz;
        const float lat = tx*ltx + ty*lty + tz*ltz;
        const float c1 = K_LON * Nmag * lon;
        const float c2 = K_LAT * Nmag * lat;
        const float ffx = c1*fwx + c2*ltx;
        const float ffy = c1*fwy + c2*lty;
        const float ffz = c1*fwz + c2*ltz;

        const float ax = fsx + ffx, ay = fsy + ffy, az = fsz + ffz;
        asx += ax; asy += ay; asz += az;
        tqx += ccy*az - ccz*ay;
        tqy += ccz*ax - ccx*az;
        tqz += ccx*ay - ccy*ax;

        const size_t p3 = ((size_t)b * NPTS + i) * 3;
        out[OFF_FS + p3 + 0] = fsx;
        out[OFF_FS + p3 + 1] = fsy;
        out[OFF_FS + p3 + 2] = fsz;
        out[OFF_FF + p3 + 0] = ffx;
        out[OFF_FF + p3 + 1] = ffy;
        out[OFF_FF + p3 + 2] = ffz;
        out[OFF_THR + p3 + 0] = thx;
        out[OFF_THR + p3 + 1] = thy;
        out[OFF_THR + p3 + 2] = thz;
    }

    {   // reduce 6 sums
        float r[6] = {asx, asy, asz, tqx, tqy, tqz};
        const int warp = tid >> 5, lane = tid & 31;
#pragma unroll
        for (int j = 0; j < 6; j++) {
            const float ws = warp_sum(r[j]);
            if (lane == 0) s_red[j*8 + warp] = ws;
        }
    }
    __syncthreads();

    // ------------------ Phase 3: solve + integrate ------------------
    if (tid == 0) {
        float as0 = 0.f, as1 = 0.f, as2 = 0.f, t0 = 0.f, t1 = 0.f, t2 = 0.f;
#pragma unroll
        for (int w8 = 0; w8 < 8; w8++) {
            as0 += s_red[0*8 + w8]; as1 += s_red[1*8 + w8]; as2 += s_red[2*8 + w8];
            t0  += s_red[3*8 + w8]; t1  += s_red[4*8 + w8]; t2  += s_red[5*8 + w8];
        }
        const float tqcx = fminf(fmaxf(t0, -TORQUE_LIM), TORQUE_LIM);
        const float tqcy = fminf(fmaxf(t1, -TORQUE_LIM), TORQUE_LIM);
        const float tqcz = fminf(fmaxf(t2, -TORQUE_LIM), TORQUE_LIM);
        out[OFF_TQ + (size_t)b*3 + 0] = tqcx;
        out[OFF_TQ + (size_t)b*3 + 1] = tqcy;
        out[OFF_TQ + (size_t)b*3 + 2] = tqcz;

        const double a00=s_inertia[0], a01=s_inertia[1], a02=s_inertia[2];
        const double a10=s_inertia[3], a11=s_inertia[4], a12=s_inertia[5];
        const double a20=s_inertia[6], a21=s_inertia[7], a22=s_inertia[8];
        const double bx=tqcx, by=tqcy, bz=tqcz;
        const double c00 = a11*a22 - a12*a21;
        const double c01 = a10*a22 - a12*a20;
        const double c02 = a10*a21 - a11*a20;
        const double det = a00*c00 - a01*c01 + a02*c02;
        const double inv = 1.0/det;
        const double odx = (bx*c00 - a01*(by*a22 - a12*bz) + a02*(by*a21 - a11*bz)) * inv;
        const double ody = (a00*(by*a22 - a12*bz) - bx*c01 + a02*(a10*bz - by*a20)) * inv;
        const double odz = (a00*(a11*bz - by*a21) - a01*(a10*bz - by*a20) + bx*c02) * inv;
        const float odxf=(float)odx, odyf=(float)ody, odzf=(float)odz;
        out[OFF_OMD + (size_t)b*3 + 0] = odxf;
        out[OFF_OMD + (size_t)b*3 + 1] = odyf;
        out[OFF_OMD + (size_t)b*3 + 2] = odzf;

        const float itm = __fdividef(1.0f, s_tm);
        const float xddx = as0 * itm;
        const float xddy = as1 * itm;
        const float xddz = (as2 - s_tm*GRAVITY) * itm;
        out[OFF_XDD + (size_t)b*3 + 0] = xddx;
        out[OFF_XDD + (size_t)b*3 + 1] = xddy;
        out[OFF_XDD + (size_t)b*3 + 2] = xddz;

        const float nxd0 = s_xd[0] + xddx*DT;
        const float nxd1 = s_xd[1] + xddy*DT;
        const float nxd2 = s_xd[2] + xddz*DT;
        out[OFF_NXD + (size_t)b*3 + 0] = nxd0;
        out[OFF_NXD + (size_t)b*3 + 1] = nxd1;
        out[OFF_NXD + (size_t)b*3 + 2] = nxd2;
        out[OFF_NX + (size_t)b*3 + 0] = s_x[0] + nxd0*DT;
        out[OFF_NX + (size_t)b*3 + 1] = s_x[1] + nxd1*DT;
        out[OFF_NX + (size_t)b*3 + 2] = s_x[2] + nxd2*DT;

        const float no0 = s_om[0] + odxf*DT;
        const float no1 = s_om[1] + odyf*DT;
        const float no2 = s_om[2] + odzf*DT;
        out[OFF_NOM + (size_t)b*3 + 0] = no0;
        out[OFF_NOM + (size_t)b*3 + 1] = no1;
        out[OFF_NOM + (size_t)b*3 + 2] = no2;

        const float aw = q_in[b*4+0], axq = q_in[b*4+1], ayq = q_in[b*4+2], azq = q_in[b*4+3];
        const float h = 0.5f * DT;
        const float dqw = h * (-(axq*no0 + ayq*no1 + azq*no2));
        const float dqx = h * ( aw*no0 + ayq*no2 - azq*no1);
        const float dqy = h * ( aw*no1 - axq*no2 + azq*no0);
        const float dqz = h * ( aw*no2 + axq*no1 - ayq*no0);
        const float nqw = aw + dqw, nqx = axq + dqx, nqy = ayq + dqy, nqz = azq + dqz;
        const float qn = sqrtf(nqw*nqw + nqx*nqx + nqy*nqy + nqz*nqz);
        const float qi = __fdividef(1.0f, qn + 1e-8f);
        out[OFF_NQ + (size_t)b*4 + 0] = nqw*qi;
        out[OFF_NQ + (size_t)b*4 + 1] = nqx*qi;
        out[OFF_NQ + (size_t)b*4 + 2] = nqy*qi;
        out[OFF_NQ + (size_t)b*4 + 3] = nqz*qi;
    }
}

extern "C" void kernel_launch(void* const* d_in, const int* in_sizes, int n_in,
                              void* d_out, int out_size)
{
    phys_kernel<<<B_, NTHREADS>>>(
        (const float*)d_in[0],  (const float*)d_in[1],  (const float*)d_in[2],
        (const float*)d_in[3],  (const float*)d_in[4],  (const float*)d_in[5],
        (const float*)d_in[6],  (const float*)d_in[7],  (const float*)d_in[8],
        (const float*)d_in[9],  (const float*)d_in[10], (const float*)d_in[11],
        (const float*)d_in[12], (const float*)d_in[13], (const float*)d_in[14],
        (const float*)d_in[15], (float*)d_out);
}